// round 3
// baseline (speedup 1.0000x reference)
#include <cuda_runtime.h>

#define B_   2
#define N_   2048
#define DIM_ 1024
#define H_   16
#define D_   64

// Scratch (device globals: allocation-free rule)
__device__ float g_qT[(size_t)B_ * H_ * D_ * N_];   // [b][h][d][i]
__device__ float g_kT[(size_t)B_ * H_ * D_ * N_];   // [b][h][d][j]
__device__ float g_v [(size_t)B_ * H_ * N_ * D_];   // [b][h][j][d]
__device__ float g_attn[(size_t)B_ * N_ * DIM_];    // [b][i][h*64+d]

// ---------------------------------------------------------------------------
// 128x128x16 fp32 GEMM, 256 threads, 8x8 micro-tile.
// mode 0: A=features, B=W_qkv (NB=3072) -> permuted store into g_qT/g_kT/g_v
// mode 1: A=g_attn,   B=W_out (NB=1024) -> plain store to Cout
// ---------------------------------------------------------------------------
__global__ __launch_bounds__(256) void gemm128(const float* __restrict__ A,
                                               const float* __restrict__ Bm,
                                               float* __restrict__ Cout,
                                               int NB, int mode) {
    __shared__ float AsT[16 * 128];   // [k][m]
    __shared__ float Bs[16 * 128];    // [k][n]  (reused as transpose stage)
    const int tid = threadIdx.x;
    const int ty = tid >> 4, tx = tid & 15;
    const int m0 = blockIdx.y * 128;
    const int n0 = blockIdx.x * 128;
    const float* Ap = (mode == 0) ? A : g_attn;
    const int K = 1024;

    const int ar = tid >> 1;            // 0..127
    const int ak = (tid & 1) * 8;       // 0 or 8
    const int bk = tid >> 4;            // 0..15
    const int bn = (tid & 15) * 8;      // 0..120

    float acc[8][8] = {};

    for (int k0 = 0; k0 < K; k0 += 16) {
        float4 av0 = *reinterpret_cast<const float4*>(&Ap[(size_t)(m0 + ar) * K + k0 + ak]);
        float4 av1 = *reinterpret_cast<const float4*>(&Ap[(size_t)(m0 + ar) * K + k0 + ak + 4]);
        AsT[(ak + 0) * 128 + ar] = av0.x; AsT[(ak + 1) * 128 + ar] = av0.y;
        AsT[(ak + 2) * 128 + ar] = av0.z; AsT[(ak + 3) * 128 + ar] = av0.w;
        AsT[(ak + 4) * 128 + ar] = av1.x; AsT[(ak + 5) * 128 + ar] = av1.y;
        AsT[(ak + 6) * 128 + ar] = av1.z; AsT[(ak + 7) * 128 + ar] = av1.w;
        *reinterpret_cast<float4*>(&Bs[bk * 128 + bn]) =
            *reinterpret_cast<const float4*>(&Bm[(size_t)(k0 + bk) * NB + n0 + bn]);
        *reinterpret_cast<float4*>(&Bs[bk * 128 + bn + 4]) =
            *reinterpret_cast<const float4*>(&Bm[(size_t)(k0 + bk) * NB + n0 + bn + 4]);
        __syncthreads();
#pragma unroll
        for (int kk = 0; kk < 16; kk++) {
            float4 a0 = *reinterpret_cast<const float4*>(&AsT[kk * 128 + ty * 8]);
            float4 a1 = *reinterpret_cast<const float4*>(&AsT[kk * 128 + ty * 8 + 4]);
            float4 b0 = *reinterpret_cast<const float4*>(&Bs[kk * 128 + tx * 8]);
            float4 b1 = *reinterpret_cast<const float4*>(&Bs[kk * 128 + tx * 8 + 4]);
            float aa[8] = {a0.x, a0.y, a0.z, a0.w, a1.x, a1.y, a1.z, a1.w};
            float bb[8] = {b0.x, b0.y, b0.z, b0.w, b1.x, b1.y, b1.z, b1.w};
#pragma unroll
            for (int ii = 0; ii < 8; ii++)
#pragma unroll
                for (int jj = 0; jj < 8; jj++) acc[ii][jj] += aa[ii] * bb[jj];
        }
        __syncthreads();
    }

    if (mode == 0) {
        const int part = n0 >> 10;          // 0=q, 1=k, 2=v (tile never crosses)
        const int b = m0 >> 11;
        const int mloc = m0 & (N_ - 1);     // row within batch
        if (part < 2) {
            float* dst = (part == 0) ? g_qT : g_kT;
            // transpose 16 columns at a time through Bs (16 x 128)
            for (int g = 0; g < 8; g++) {
                __syncthreads();
                if ((tx >> 1) == g) {
                    const int c0 = (tx & 1) * 8;
#pragma unroll
                    for (int jj = 0; jj < 8; jj++)
#pragma unroll
                        for (int ii = 0; ii < 8; ii++)
                            Bs[(c0 + jj) * 128 + ty * 8 + ii] = acc[ii][jj];
                }
                __syncthreads();
                const int cr = tid >> 4;          // col within chunk 0..15
                const int io = (tid & 15) * 8;    // row offset 0..120
                const int c = n0 + g * 16 + cr;
                const int hh = (c & 1023) >> 6;
                const int d = c & 63;
                float* dp = dst + ((size_t)(b * H_ + hh) * D_ + d) * N_ + mloc + io;
                *reinterpret_cast<float4*>(dp) =
                    *reinterpret_cast<const float4*>(&Bs[cr * 128 + io]);
                *reinterpret_cast<float4*>(dp + 4) =
                    *reinterpret_cast<const float4*>(&Bs[cr * 128 + io + 4]);
            }
        } else {
            const size_t base = (size_t)(b * H_) * N_ * D_;  // + h*N*D added per col
#pragma unroll
            for (int ii = 0; ii < 8; ii++) {
                const int i = mloc + ty * 8 + ii;
#pragma unroll
                for (int jc = 0; jc < 2; jc++) {
                    const int c = n0 + tx * 8 + jc * 4;      // 4-aligned, one head
                    const int hh = (c & 1023) >> 6;
                    const int d = c & 63;
                    *reinterpret_cast<float4*>(
                        &g_v[base + (size_t)hh * N_ * D_ + (size_t)i * D_ + d]) =
                        make_float4(acc[ii][jc * 4 + 0], acc[ii][jc * 4 + 1],
                                    acc[ii][jc * 4 + 2], acc[ii][jc * 4 + 3]);
                }
            }
        }
    } else {
#pragma unroll
        for (int ii = 0; ii < 8; ii++) {
            const int m = m0 + ty * 8 + ii;
            *reinterpret_cast<float4*>(&Cout[(size_t)m * NB + n0 + tx * 8]) =
                make_float4(acc[ii][0], acc[ii][1], acc[ii][2], acc[ii][3]);
            *reinterpret_cast<float4*>(&Cout[(size_t)m * NB + n0 + tx * 8 + 4]) =
                make_float4(acc[ii][4], acc[ii][5], acc[ii][6], acc[ii][7]);
        }
    }
}

// ---------------------------------------------------------------------------
// Fused segment attention. One block = 128 query rows of one (b,h).
// Pass 1: per-(row,seg) denominators of exp(qk/32).
// Pass 2: w = e * inv_denom[row][mask], O += w @ V.
// 256 threads, 8 rows x 4 cols per thread.
// ---------------------------------------------------------------------------
__global__ __launch_bounds__(256) void attn_kernel(const int* __restrict__ mask) {
    extern __shared__ float sm[];
    float* qsT  = sm;             // [64][128]  8192 f
    float* ksT  = sm + 8192;      // [64][64]   4096 f
    float* vs   = sm + 12288;     // [64][64]   4096 f
    float* ws   = sm + 16384;     // [128][64]  8192 f
    float* dsh  = sm + 24576;     // [128][4]    512 f
    float* invd = sm + 25088;     // [128][4]    512 f

    const int b = blockIdx.z, h = blockIdx.x;
    const int i0 = blockIdx.y * 128;
    const int tid = threadIdx.x;
    const int ty = tid >> 4, tx = tid & 15;

    const size_t tb = (size_t)(b * H_ + h) * D_ * N_;
    const float* vbase = g_v + (size_t)(b * H_ + h) * N_ * D_;
    const int* mrow = mask + (size_t)b * N_ * N_ + (size_t)i0 * N_;

    // load Q tile, pre-scaled by 1/32 (exact power of 2)
    const float SC = 1.0f / 32.0f;
    for (int t = tid; t < 2048; t += 256) {
        const int d = t >> 5, rb = (t & 31) * 4;
        float4 qv = *reinterpret_cast<const float4*>(&g_qT[tb + (size_t)d * N_ + i0 + rb]);
        qv.x *= SC; qv.y *= SC; qv.z *= SC; qv.w *= SC;
        *reinterpret_cast<float4*>(&qsT[d * 128 + rb]) = qv;
    }
    for (int t = tid; t < 512; t += 256) dsh[t] = 0.0f;
    __syncthreads();

#define LOAD_KT(j0)                                                              \
    for (int t = tid; t < 1024; t += 256) {                                      \
        const int d = t >> 4, cb = (t & 15) * 4;                                 \
        *reinterpret_cast<float4*>(&ksT[d * 64 + cb]) =                          \
            *reinterpret_cast<const float4*>(&g_kT[tb + (size_t)d * N_ + (j0) + cb]); \
    }

#define SCORES(S)                                                                \
    {                                                                            \
        _Pragma("unroll 4") for (int d = 0; d < 64; d++) {                       \
            float4 a0 = *reinterpret_cast<const float4*>(&qsT[d * 128 + ty * 8]); \
            float4 a1 = *reinterpret_cast<const float4*>(&qsT[d * 128 + ty * 8 + 4]); \
            float4 k4 = *reinterpret_cast<const float4*>(&ksT[d * 64 + tx * 4]); \
            float aa[8] = {a0.x, a0.y, a0.z, a0.w, a1.x, a1.y, a1.z, a1.w};      \
            float kk_[4] = {k4.x, k4.y, k4.z, k4.w};                             \
            _Pragma("unroll") for (int ii = 0; ii < 8; ii++)                     \
                _Pragma("unroll") for (int jj = 0; jj < 4; jj++)                 \
                    S[ii][jj] += aa[ii] * kk_[jj];                               \
        }                                                                        \
    }

    // ---------------- PASS 1: denominators ----------------
    {
        float dsum[8][4] = {};
        for (int j0 = 0; j0 < N_; j0 += 64) {
            LOAD_KT(j0);
            __syncthreads();
            float s[8][4] = {};
            SCORES(s);
#pragma unroll
            for (int ii = 0; ii < 8; ii++) {
                const int r = ty * 8 + ii;
                const int4 mm = *reinterpret_cast<const int4*>(
                    &mrow[(size_t)r * N_ + j0 + tx * 4]);
                float e0 = __expf(s[ii][0]), e1 = __expf(s[ii][1]);
                float e2 = __expf(s[ii][2]), e3 = __expf(s[ii][3]);
#define ACC1(SG, E)                                                              \
                if ((SG) == 0) dsum[ii][0] += (E);                               \
                else if ((SG) == 1) dsum[ii][1] += (E);                          \
                else if ((SG) == 2) dsum[ii][2] += (E);                          \
                else dsum[ii][3] += (E);
                ACC1(mm.x, e0) ACC1(mm.y, e1) ACC1(mm.z, e2) ACC1(mm.w, e3)
#undef ACC1
            }
            __syncthreads();
        }
#pragma unroll
        for (int ii = 0; ii < 8; ii++)
#pragma unroll
            for (int ss = 0; ss < 4; ss++)
                atomicAdd(&dsh[(ty * 8 + ii) * 4 + ss], dsum[ii][ss]);
    }
    __syncthreads();
    for (int t = tid; t < 512; t += 256) {
        const float dv = dsh[t];
        invd[t] = (dv == 0.0f) ? 1.0f : 1.0f / dv;
    }
    __syncthreads();

    // ---------------- PASS 2: O = w @ V ----------------
    float o[8][4] = {};
    for (int j0 = 0; j0 < N_; j0 += 64) {
        LOAD_KT(j0);
        {
            const float4* vsrc = reinterpret_cast<const float4*>(vbase + (size_t)j0 * D_);
            for (int t = tid; t < 1024; t += 256)
                reinterpret_cast<float4*>(vs)[t] = vsrc[t];
        }
        __syncthreads();
        float s[8][4] = {};
        SCORES(s);
#pragma unroll
        for (int ii = 0; ii < 8; ii++) {
            const int r = ty * 8 + ii;
            const int4 mm = *reinterpret_cast<const int4*>(
                &mrow[(size_t)r * N_ + j0 + tx * 4]);
            const float w0 = __expf(s[ii][0]) * invd[r * 4 + mm.x];
            const float w1 = __expf(s[ii][1]) * invd[r * 4 + mm.y];
            const float w2 = __expf(s[ii][2]) * invd[r * 4 + mm.z];
            const float w3 = __expf(s[ii][3]) * invd[r * 4 + mm.w];
            *reinterpret_cast<float4*>(&ws[r * 64 + tx * 4]) =
                make_float4(w0, w1, w2, w3);
        }
        __syncthreads();
#pragma unroll 2
        for (int jc = 0; jc < 16; jc++) {
            float4 v0 = *reinterpret_cast<const float4*>(&vs[(jc * 4 + 0) * 64 + tx * 4]);
            float4 v1 = *reinterpret_cast<const float4*>(&vs[(jc * 4 + 1) * 64 + tx * 4]);
            float4 v2 = *reinterpret_cast<const float4*>(&vs[(jc * 4 + 2) * 64 + tx * 4]);
            float4 v3 = *reinterpret_cast<const float4*>(&vs[(jc * 4 + 3) * 64 + tx * 4]);
#pragma unroll
            for (int ii = 0; ii < 8; ii++) {
                const int r = ty * 8 + ii;
                const float4 w4 = *reinterpret_cast<const float4*>(&ws[r * 64 + jc * 4]);
                o[ii][0] += w4.x * v0.x; o[ii][1] += w4.x * v0.y;
                o[ii][2] += w4.x * v0.z; o[ii][3] += w4.x * v0.w;
                o[ii][0] += w4.y * v1.x; o[ii][1] += w4.y * v1.y;
                o[ii][2] += w4.y * v1.z; o[ii][3] += w4.y * v1.w;
                o[ii][0] += w4.z * v2.x; o[ii][1] += w4.z * v2.y;
                o[ii][2] += w4.z * v2.z; o[ii][3] += w4.z * v2.w;
                o[ii][0] += w4.w * v3.x; o[ii][1] += w4.w * v3.y;
                o[ii][2] += w4.w * v3.z; o[ii][3] += w4.w * v3.w;
            }
        }
        __syncthreads();
    }
#pragma unroll
    for (int ii = 0; ii < 8; ii++) {
        const int i = i0 + ty * 8 + ii;
        *reinterpret_cast<float4*>(
            &g_attn[(size_t)(b * N_ + i) * DIM_ + h * D_ + tx * 4]) =
            make_float4(o[ii][0], o[ii][1], o[ii][2], o[ii][3]);
    }
#undef SCORES
#undef LOAD_KT
}

// ---------------------------------------------------------------------------
extern "C" void kernel_launch(void* const* d_in, const int* in_sizes, int n_in,
                              void* d_out, int out_size) {
    const float* features = (const float*)d_in[0];
    const int*   mask     = (const int*)d_in[1];
    const float* W_qkv    = (const float*)d_in[2];
    const float* W_out    = (const float*)d_in[3];
    float* out = (float*)d_out;

    cudaFuncSetAttribute(attn_kernel, cudaFuncAttributeMaxDynamicSharedMemorySize,
                         102400);

    // qkv = features @ W_qkv  (permuted store into g_qT/g_kT/g_v)
    gemm128<<<dim3(3072 / 128, (B_ * N_) / 128), 256>>>(features, W_qkv, nullptr, 3072, 0);
    // fused masked-segment attention -> g_attn
    attn_kernel<<<dim3(H_, N_ / 128, B_), 256, 102400>>>(mask);
    // out = g_attn @ W_out
    gemm128<<<dim3(DIM_ / 128, (B_ * N_) / 128), 256>>>(nullptr, W_out, out, DIM_, 1);
}

// round 4
// speedup vs baseline: 1.4938x; 1.4938x over previous
#include <cuda_runtime.h>
#include <cuda_bf16.h>

#define B_   2
#define N_   2048
#define DIM_ 1024
#define H_   16
#define D_   64
#define BH_  (B_ * H_)

// bf16 split tensors (device globals: allocation-free rule)
__device__ __nv_bfloat16 g_qh[(size_t)BH_ * N_ * D_];   // [bh][i][d] (q/32)
__device__ __nv_bfloat16 g_ql[(size_t)BH_ * N_ * D_];
__device__ __nv_bfloat16 g_kh[(size_t)BH_ * N_ * D_];   // [bh][j][d]
__device__ __nv_bfloat16 g_kl[(size_t)BH_ * N_ * D_];
__device__ __nv_bfloat16 g_vh[(size_t)BH_ * D_ * N_];   // [bh][d][j]  (transposed)
__device__ __nv_bfloat16 g_vl[(size_t)BH_ * D_ * N_];
__device__ float g_attn[(size_t)B_ * N_ * DIM_];        // [b][i][h*64+d]

__device__ __forceinline__ unsigned b2u(__nv_bfloat162 v) {
    return *reinterpret_cast<unsigned*>(&v);
}
__device__ __forceinline__ void split2(float x0, float x1, unsigned& hi, unsigned& lo) {
    __nv_bfloat162 h2 = __floats2bfloat162_rn(x0, x1);
    __nv_bfloat162 l2 = __floats2bfloat162_rn(x0 - __bfloat162float(h2.x),
                                              x1 - __bfloat162float(h2.y));
    hi = b2u(h2); lo = b2u(l2);
}

__device__ __forceinline__ void mma16816(float* c, unsigned a0, unsigned a1,
                                         unsigned a2, unsigned a3,
                                         unsigned b0, unsigned b1) {
    asm("mma.sync.aligned.m16n8k16.row.col.f32.bf16.bf16.f32 "
        "{%0,%1,%2,%3},{%4,%5,%6,%7},{%8,%9},{%0,%1,%2,%3};\n"
        : "+f"(c[0]), "+f"(c[1]), "+f"(c[2]), "+f"(c[3])
        : "r"(a0), "r"(a1), "r"(a2), "r"(a3), "r"(b0), "r"(b1));
}

// m128 x n64 x k64 block-MMA with hi/lo split (3 products), smem stride 36 words.
// A at AH/AL (rows = arow+g, +8), B at BH/BL (rows = n-index).
__device__ __forceinline__ void mma_tile(const unsigned* su, int AH, int AL,
                                         int BHo, int BLo, int arow, int g, int t,
                                         float c[8][4]) {
#pragma unroll
    for (int ks = 0; ks < 4; ks++) {
        const int ar = (arow + g) * 36 + ks * 8 + t;
        unsigned ah0 = su[AH + ar],       ah1 = su[AH + ar + 288];
        unsigned ah2 = su[AH + ar + 4],   ah3 = su[AH + ar + 292];
        unsigned al0 = su[AL + ar],       al1 = su[AL + ar + 288];
        unsigned al2 = su[AL + ar + 4],   al3 = su[AL + ar + 292];
#pragma unroll
        for (int nt = 0; nt < 8; nt++) {
            const int br = (nt * 8 + g) * 36 + ks * 8 + t;
            unsigned bh0 = su[BHo + br], bh1 = su[BHo + br + 4];
            unsigned bl0 = su[BLo + br], bl1 = su[BLo + br + 4];
            mma16816(c[nt], ah0, ah1, ah2, ah3, bh0, bh1);
            mma16816(c[nt], ah0, ah1, ah2, ah3, bl0, bl1);
            mma16816(c[nt], al0, al1, al2, al3, bh0, bh1);
        }
    }
}

// ---------------------------------------------------------------------------
// 128x128x16 fp32 GEMM, 256 threads, 8x8 micro-tile.
// mode 0: qkv -> bf16-split permuted stores. mode 1: plain fp32 store.
// ---------------------------------------------------------------------------
__global__ __launch_bounds__(256) void gemm128(const float* __restrict__ A,
                                               const float* __restrict__ Bm,
                                               float* __restrict__ Cout,
                                               int NB, int mode) {
    __shared__ float AsT[16 * 128];
    __shared__ float Bs[16 * 128];
    const int tid = threadIdx.x;
    const int ty = tid >> 4, tx = tid & 15;
    const int m0 = blockIdx.y * 128;
    const int n0 = blockIdx.x * 128;
    const float* Ap = (mode == 0) ? A : g_attn;
    const int K = 1024;

    const int ar = tid >> 1;
    const int ak = (tid & 1) * 8;
    const int bk = tid >> 4;
    const int bn = (tid & 15) * 8;

    float acc[8][8] = {};

    for (int k0 = 0; k0 < K; k0 += 16) {
        float4 av0 = *reinterpret_cast<const float4*>(&Ap[(size_t)(m0 + ar) * K + k0 + ak]);
        float4 av1 = *reinterpret_cast<const float4*>(&Ap[(size_t)(m0 + ar) * K + k0 + ak + 4]);
        AsT[(ak + 0) * 128 + ar] = av0.x; AsT[(ak + 1) * 128 + ar] = av0.y;
        AsT[(ak + 2) * 128 + ar] = av0.z; AsT[(ak + 3) * 128 + ar] = av0.w;
        AsT[(ak + 4) * 128 + ar] = av1.x; AsT[(ak + 5) * 128 + ar] = av1.y;
        AsT[(ak + 6) * 128 + ar] = av1.z; AsT[(ak + 7) * 128 + ar] = av1.w;
        *reinterpret_cast<float4*>(&Bs[bk * 128 + bn]) =
            *reinterpret_cast<const float4*>(&Bm[(size_t)(k0 + bk) * NB + n0 + bn]);
        *reinterpret_cast<float4*>(&Bs[bk * 128 + bn + 4]) =
            *reinterpret_cast<const float4*>(&Bm[(size_t)(k0 + bk) * NB + n0 + bn + 4]);
        __syncthreads();
#pragma unroll
        for (int kk = 0; kk < 16; kk++) {
            float4 a0 = *reinterpret_cast<const float4*>(&AsT[kk * 128 + ty * 8]);
            float4 a1 = *reinterpret_cast<const float4*>(&AsT[kk * 128 + ty * 8 + 4]);
            float4 b0 = *reinterpret_cast<const float4*>(&Bs[kk * 128 + tx * 8]);
            float4 b1 = *reinterpret_cast<const float4*>(&Bs[kk * 128 + tx * 8 + 4]);
            float aa[8] = {a0.x, a0.y, a0.z, a0.w, a1.x, a1.y, a1.z, a1.w};
            float bb[8] = {b0.x, b0.y, b0.z, b0.w, b1.x, b1.y, b1.z, b1.w};
#pragma unroll
            for (int ii = 0; ii < 8; ii++)
#pragma unroll
                for (int jj = 0; jj < 8; jj++) acc[ii][jj] += aa[ii] * bb[jj];
        }
        __syncthreads();
    }

    if (mode == 0) {
        const int part = n0 >> 10;          // 0=q, 1=k, 2=v
        const int b = m0 >> 11;
        const int mloc = m0 & (N_ - 1);
        if (part < 2) {
            const float SCp = (part == 0) ? 0.03125f : 1.0f;
            __nv_bfloat16* dh = (part == 0) ? g_qh : g_kh;
            __nv_bfloat16* dl = (part == 0) ? g_ql : g_kl;
            const int c0 = n0 + tx * 8;
            const int hh = (c0 & 1023) >> 6;
            const int d0 = c0 & 63;
#pragma unroll
            for (int ii = 0; ii < 8; ii++) {
                const int i = mloc + ty * 8 + ii;
                unsigned uh[4], ul[4];
#pragma unroll
                for (int p = 0; p < 4; p++)
                    split2(acc[ii][2 * p] * SCp, acc[ii][2 * p + 1] * SCp, uh[p], ul[p]);
                const size_t off = ((size_t)(b * H_ + hh) * N_ + i) * D_ + d0;
                *reinterpret_cast<uint4*>(dh + off) = make_uint4(uh[0], uh[1], uh[2], uh[3]);
                *reinterpret_cast<uint4*>(dl + off) = make_uint4(ul[0], ul[1], ul[2], ul[3]);
            }
        } else {
            // v: transpose through Bs, store [bh][d][n] bf16 hi/lo
            for (int g16 = 0; g16 < 8; g16++) {
                __syncthreads();
                if ((tx >> 1) == g16) {
                    const int cc0 = (tx & 1) * 8;
#pragma unroll
                    for (int jj = 0; jj < 8; jj++)
#pragma unroll
                        for (int ii = 0; ii < 8; ii++)
                            Bs[(cc0 + jj) * 128 + ty * 8 + ii] = acc[ii][jj];
                }
                __syncthreads();
                const int cr = tid >> 4;
                const int io = (tid & 15) * 8;
                const int c = n0 + g16 * 16 + cr;
                const int hh = (c & 1023) >> 6;
                const int d = c & 63;
                const float* src = &Bs[cr * 128 + io];
                unsigned uh[4], ul[4];
#pragma unroll
                for (int p = 0; p < 4; p++)
                    split2(src[2 * p], src[2 * p + 1], uh[p], ul[p]);
                const size_t off = ((size_t)(b * H_ + hh) * D_ + d) * N_ + mloc + io;
                *reinterpret_cast<uint4*>(g_vh + off) = make_uint4(uh[0], uh[1], uh[2], uh[3]);
                *reinterpret_cast<uint4*>(g_vl + off) = make_uint4(ul[0], ul[1], ul[2], ul[3]);
            }
        }
    } else {
#pragma unroll
        for (int ii = 0; ii < 8; ii++) {
            const int m = m0 + ty * 8 + ii;
            *reinterpret_cast<float4*>(&Cout[(size_t)m * NB + n0 + tx * 8]) =
                make_float4(acc[ii][0], acc[ii][1], acc[ii][2], acc[ii][3]);
            *reinterpret_cast<float4*>(&Cout[(size_t)m * NB + n0 + tx * 8 + 4]) =
                make_float4(acc[ii][4], acc[ii][5], acc[ii][6], acc[ii][7]);
        }
    }
}

// ---------------------------------------------------------------------------
// Tensor-core segment attention: 128 rows x full N per block, 8 warps.
// Smem word layout (stride 36 words = 72 bf16 per row, conflict-free):
//  QH 0, QL 4608, KH 9216, KL 11520, VH 13824, VL 16128, WH 18432, WL 23040,
//  DSH 27648 (512 f), INV 28160 (512 f) -> total 28672 words = 114688 B
// ---------------------------------------------------------------------------
#define SQH 0
#define SQL 4608
#define SKH 9216
#define SKL 11520
#define SVH 13824
#define SVL 16128
#define SWH 18432
#define SWL 23040

#define ACCSEG(DS, SG, E)                                                      \
    { if ((SG) == 0) DS[0] += (E); else if ((SG) == 1) DS[1] += (E);           \
      else if ((SG) == 2) DS[2] += (E); else DS[3] += (E); }

__global__ __launch_bounds__(256, 2) void attn_mma(const int* __restrict__ mask) {
    extern __shared__ unsigned su[];
    float* dshf = reinterpret_cast<float*>(su + 27648);
    float* invf = reinterpret_cast<float*>(su + 28160);
    uint4* su4 = reinterpret_cast<uint4*>(su);

    const int b = blockIdx.z, h = blockIdx.x;
    const int i0 = blockIdx.y * 128;
    const int bh = b * H_ + h;
    const int tid = threadIdx.x;
    const int lane = tid & 31, wp = tid >> 5;
    const int g = lane >> 2, t = lane & 3;
    const int r0 = wp * 16 + g, r1 = r0 + 8;
    const int* mrow = mask + (size_t)b * N_ * N_ + (size_t)i0 * N_;

    // load Q tile (hi/lo) once
    {
        const uint4* gqh = reinterpret_cast<const uint4*>(g_qh + ((size_t)bh * N_ + i0) * D_);
        const uint4* gql = reinterpret_cast<const uint4*>(g_ql + ((size_t)bh * N_ + i0) * D_);
        for (int idx = tid; idx < 1024; idx += 256) {
            const int r = idx >> 3, c = idx & 7;
            su4[(SQH >> 2) + r * 9 + c] = gqh[idx];
            su4[(SQL >> 2) + r * 9 + c] = gql[idx];
        }
    }

    // ---------------- PASS 1: denominators ----------------
    float ds0[4] = {0.f, 0.f, 0.f, 0.f}, ds1[4] = {0.f, 0.f, 0.f, 0.f};
    for (int j0 = 0; j0 < N_; j0 += 64) {
        const uint4* gkh = reinterpret_cast<const uint4*>(g_kh + ((size_t)bh * N_ + j0) * D_);
        const uint4* gkl = reinterpret_cast<const uint4*>(g_kl + ((size_t)bh * N_ + j0) * D_);
        for (int idx = tid; idx < 512; idx += 256) {
            const int r = idx >> 3, c = idx & 7;
            su4[(SKH >> 2) + r * 9 + c] = gkh[idx];
            su4[(SKL >> 2) + r * 9 + c] = gkl[idx];
        }
        __syncthreads();
        float c8[8][4] = {};
        mma_tile(su, SQH, SQL, SKH, SKL, wp * 16, g, t, c8);
#pragma unroll
        for (int nt = 0; nt < 8; nt++) {
            const int jc = j0 + nt * 8 + 2 * t;
            const int2 m0 = *reinterpret_cast<const int2*>(&mrow[(size_t)r0 * N_ + jc]);
            const int2 m1 = *reinterpret_cast<const int2*>(&mrow[(size_t)r1 * N_ + jc]);
            const float e0 = __expf(c8[nt][0]), e1 = __expf(c8[nt][1]);
            const float e2 = __expf(c8[nt][2]), e3 = __expf(c8[nt][3]);
            ACCSEG(ds0, m0.x, e0) ACCSEG(ds0, m0.y, e1)
            ACCSEG(ds1, m1.x, e2) ACCSEG(ds1, m1.y, e3)
        }
        __syncthreads();
    }
#pragma unroll
    for (int s = 0; s < 4; s++) {
        float v0 = ds0[s], v1 = ds1[s];
        v0 += __shfl_xor_sync(0xffffffffu, v0, 1);
        v0 += __shfl_xor_sync(0xffffffffu, v0, 2);
        v1 += __shfl_xor_sync(0xffffffffu, v1, 1);
        v1 += __shfl_xor_sync(0xffffffffu, v1, 2);
        if (t == 0) { dshf[r0 * 4 + s] = v0; dshf[r1 * 4 + s] = v1; }
    }
    __syncthreads();
    for (int idx = tid; idx < 512; idx += 256) {
        const float dv = dshf[idx];
        invf[idx] = (dv == 0.0f) ? 1.0f : 1.0f / dv;
    }
    __syncthreads();

    // ---------------- PASS 2: w = e*invd -> O += w @ V ----------------
    float o8[8][4] = {};
    for (int j0 = 0; j0 < N_; j0 += 64) {
        const uint4* gkh = reinterpret_cast<const uint4*>(g_kh + ((size_t)bh * N_ + j0) * D_);
        const uint4* gkl = reinterpret_cast<const uint4*>(g_kl + ((size_t)bh * N_ + j0) * D_);
        const uint4* gvh = reinterpret_cast<const uint4*>(g_vh);
        const uint4* gvl = reinterpret_cast<const uint4*>(g_vl);
        for (int idx = tid; idx < 512; idx += 256) {
            const int r = idx >> 3, c = idx & 7;
            su4[(SKH >> 2) + r * 9 + c] = gkh[idx];
            su4[(SKL >> 2) + r * 9 + c] = gkl[idx];
            const size_t vi = ((size_t)bh * D_ + r) * 256 + (j0 >> 3) + c;
            su4[(SVH >> 2) + r * 9 + c] = gvh[vi];
            su4[(SVL >> 2) + r * 9 + c] = gvl[vi];
        }
        __syncthreads();
        float c8[8][4] = {};
        mma_tile(su, SQH, SQL, SKH, SKL, wp * 16, g, t, c8);
#pragma unroll
        for (int nt = 0; nt < 8; nt++) {
            const int jc = j0 + nt * 8 + 2 * t;
            const int2 m0 = *reinterpret_cast<const int2*>(&mrow[(size_t)r0 * N_ + jc]);
            const int2 m1 = *reinterpret_cast<const int2*>(&mrow[(size_t)r1 * N_ + jc]);
            const float w00 = __expf(c8[nt][0]) * invf[r0 * 4 + m0.x];
            const float w01 = __expf(c8[nt][1]) * invf[r0 * 4 + m0.y];
            const float w10 = __expf(c8[nt][2]) * invf[r1 * 4 + m1.x];
            const float w11 = __expf(c8[nt][3]) * invf[r1 * 4 + m1.y];
            unsigned hi, lo;
            split2(w00, w01, hi, lo);
            su[SWH + r0 * 36 + nt * 4 + t] = hi;
            su[SWL + r0 * 36 + nt * 4 + t] = lo;
            split2(w10, w11, hi, lo);
            su[SWH + r1 * 36 + nt * 4 + t] = hi;
            su[SWL + r1 * 36 + nt * 4 + t] = lo;
        }
        __syncwarp();
        mma_tile(su, SWH, SWL, SVH, SVL, wp * 16, g, t, o8);
        __syncthreads();
    }

    // store O
#pragma unroll
    for (int nt = 0; nt < 8; nt++) {
        const size_t base =
            ((size_t)(b * N_ + i0 + r0)) * DIM_ + h * 64 + nt * 8 + 2 * t;
        *reinterpret_cast<float2*>(&g_attn[base]) = make_float2(o8[nt][0], o8[nt][1]);
        *reinterpret_cast<float2*>(&g_attn[base + (size_t)8 * DIM_]) =
            make_float2(o8[nt][2], o8[nt][3]);
    }
}

// ---------------------------------------------------------------------------
extern "C" void kernel_launch(void* const* d_in, const int* in_sizes, int n_in,
                              void* d_out, int out_size) {
    const float* features = (const float*)d_in[0];
    const int*   mask     = (const int*)d_in[1];
    const float* W_qkv    = (const float*)d_in[2];
    const float* W_out    = (const float*)d_in[3];
    float* out = (float*)d_out;

    cudaFuncSetAttribute(attn_mma, cudaFuncAttributeMaxDynamicSharedMemorySize,
                         114688);

    // qkv = features @ W_qkv  -> bf16-split q/k/v (permuted)
    gemm128<<<dim3(3072 / 128, (B_ * N_) / 128), 256>>>(features, W_qkv, nullptr, 3072, 0);
    // fused masked-segment attention (tensor cores) -> g_attn
    attn_mma<<<dim3(H_, N_ / 128, B_), 256, 114688>>>(mask);
    // out = g_attn @ W_out  (fp32)
    gemm128<<<dim3(DIM_ / 128, (B_ * N_) / 128), 256>>>(nullptr, W_out, out, DIM_, 1);
}

// round 5
// speedup vs baseline: 1.9620x; 1.3134x over previous
#include <cuda_runtime.h>
#include <cuda_bf16.h>

#define B_   2
#define N_   2048
#define DIM_ 1024
#define H_   16
#define D_   64
#define BH_  (B_ * H_)
#define M_   (B_ * N_)

// ---- device scratch (allocation-free rule) ----
__device__ __nv_bfloat16 g_fh[(size_t)M_ * DIM_];        // features split
__device__ __nv_bfloat16 g_fl[(size_t)M_ * DIM_];
__device__ __nv_bfloat16 g_wqh[(size_t)3 * DIM_ * DIM_]; // W_qkv^T [3072][1024]
__device__ __nv_bfloat16 g_wql[(size_t)3 * DIM_ * DIM_];
__device__ __nv_bfloat16 g_woh[(size_t)DIM_ * DIM_];     // W_out^T [1024][1024]
__device__ __nv_bfloat16 g_wol[(size_t)DIM_ * DIM_];
__device__ __nv_bfloat16 g_qh[(size_t)BH_ * N_ * D_];    // [bh][i][d] (q/32)
__device__ __nv_bfloat16 g_ql[(size_t)BH_ * N_ * D_];
__device__ __nv_bfloat16 g_kh[(size_t)BH_ * N_ * D_];    // [bh][j][d]
__device__ __nv_bfloat16 g_kl[(size_t)BH_ * N_ * D_];
__device__ __nv_bfloat16 g_vh[(size_t)BH_ * D_ * N_];    // [bh][d][j]
__device__ __nv_bfloat16 g_vl[(size_t)BH_ * D_ * N_];
__device__ __nv_bfloat16 g_ah[(size_t)M_ * DIM_];        // attn out split
__device__ __nv_bfloat16 g_al[(size_t)M_ * DIM_];

__device__ __forceinline__ unsigned b2u(__nv_bfloat162 v) {
    return *reinterpret_cast<unsigned*>(&v);
}
__device__ __forceinline__ void split2(float x0, float x1, unsigned& hi, unsigned& lo) {
    __nv_bfloat162 h2 = __floats2bfloat162_rn(x0, x1);
    __nv_bfloat162 l2 = __floats2bfloat162_rn(x0 - __bfloat162float(h2.x),
                                              x1 - __bfloat162float(h2.y));
    hi = b2u(h2); lo = b2u(l2);
}

__device__ __forceinline__ void mma16816(float* c, unsigned a0, unsigned a1,
                                         unsigned a2, unsigned a3,
                                         unsigned b0, unsigned b1) {
    asm("mma.sync.aligned.m16n8k16.row.col.f32.bf16.bf16.f32 "
        "{%0,%1,%2,%3},{%4,%5,%6,%7},{%8,%9},{%0,%1,%2,%3};\n"
        : "+f"(c[0]), "+f"(c[1]), "+f"(c[2]), "+f"(c[3])
        : "r"(a0), "r"(a1), "r"(a2), "r"(a3), "r"(b0), "r"(b1));
}

// m16(rows arow+g/+8) x n64 x k64 with hi/lo split (3 products), stride 36 words.
__device__ __forceinline__ void mma_tile(const unsigned* su, int AH, int AL,
                                         int BHo, int BLo, int arow, int g, int t,
                                         float c[8][4]) {
#pragma unroll
    for (int ks = 0; ks < 4; ks++) {
        const int ar = (arow + g) * 36 + ks * 8 + t;
        unsigned ah0 = su[AH + ar],       ah1 = su[AH + ar + 288];
        unsigned ah2 = su[AH + ar + 4],   ah3 = su[AH + ar + 292];
        unsigned al0 = su[AL + ar],       al1 = su[AL + ar + 288];
        unsigned al2 = su[AL + ar + 4],   al3 = su[AL + ar + 292];
#pragma unroll
        for (int nt = 0; nt < 8; nt++) {
            const int br = (nt * 8 + g) * 36 + ks * 8 + t;
            unsigned bh0 = su[BHo + br], bh1 = su[BHo + br + 4];
            unsigned bl0 = su[BLo + br], bl1 = su[BLo + br + 4];
            mma16816(c[nt], ah0, ah1, ah2, ah3, bh0, bh1);
            mma16816(c[nt], ah0, ah1, ah2, ah3, bl0, bl1);
            mma16816(c[nt], al0, al1, al2, al3, bh0, bh1);
        }
    }
}

// ---------------- preprocess: splits ----------------
__global__ __launch_bounds__(256) void split_f32(const float* __restrict__ src,
                                                 __nv_bfloat16* __restrict__ dh,
                                                 __nv_bfloat16* __restrict__ dl,
                                                 int n2) {
    int i = blockIdx.x * 256 + threadIdx.x;
    if (i < n2) {
        float2 v = reinterpret_cast<const float2*>(src)[i];
        unsigned hi, lo; split2(v.x, v.y, hi, lo);
        reinterpret_cast<unsigned*>(dh)[i] = hi;
        reinterpret_cast<unsigned*>(dl)[i] = lo;
    }
}

// W [K x NB] -> W^T split [NB x K]
__global__ __launch_bounds__(256) void tsplit_w(const float* __restrict__ W,
                                                __nv_bfloat16* __restrict__ dh,
                                                __nv_bfloat16* __restrict__ dl,
                                                int K, int NB) {
    __shared__ float tile[32][33];
    const int n0 = blockIdx.x * 32, k0 = blockIdx.y * 32;
    const int tx = threadIdx.x & 31, ty = threadIdx.x >> 5;
    for (int r = ty; r < 32; r += 8)
        tile[r][tx] = W[(size_t)(k0 + r) * NB + n0 + tx];
    __syncthreads();
    for (int u = threadIdx.x; u < 512; u += 256) {
        const int rr = u >> 4, c = (u & 15) * 2;
        unsigned hi, lo; split2(tile[c][rr], tile[c + 1][rr], hi, lo);
        const size_t off = ((size_t)(n0 + rr) * K + k0 + c) >> 1;
        reinterpret_cast<unsigned*>(dh)[off] = hi;
        reinterpret_cast<unsigned*>(dl)[off] = lo;
    }
}

// ---------------- tensor-core GEMM: 128m x 64n, K=1024 ----------------
// smem words: AH 0, AL 4608, BH 9216, BL 11520 ; total 13824 w = 55296 B
#define SAH 0
#define SAL 4608
#define SBH 9216
#define SBL 11520

__global__ __launch_bounds__(256, 2) void mma_gemm(
    const __nv_bfloat16* __restrict__ Ah, const __nv_bfloat16* __restrict__ Al,
    const __nv_bfloat16* __restrict__ Bh, const __nv_bfloat16* __restrict__ Bl,
    float* __restrict__ Cout, int mode) {
    extern __shared__ unsigned su[];
    uint4* su4 = reinterpret_cast<uint4*>(su);
    const int K = 1024;
    const int m0 = blockIdx.y * 128, n0 = blockIdx.x * 64;
    const int tid = threadIdx.x, lane = tid & 31, wp = tid >> 5;
    const int g = lane >> 2, t = lane & 3;
    const int r0 = wp * 16 + g, r1 = r0 + 8;

    float c8[8][4] = {};

    const uint4* pAh = reinterpret_cast<const uint4*>(Ah + (size_t)m0 * K);
    const uint4* pAl = reinterpret_cast<const uint4*>(Al + (size_t)m0 * K);
    const uint4* pBh = reinterpret_cast<const uint4*>(Bh + (size_t)n0 * K);
    const uint4* pBl = reinterpret_cast<const uint4*>(Bl + (size_t)n0 * K);

    for (int k0 = 0; k0 < K; k0 += 64) {
        const int kc = k0 >> 3;   // uint4 offset within a row
        for (int idx = tid; idx < 1024; idx += 256) {
            const int r = idx >> 3, c = idx & 7;
            const size_t go = (size_t)r * 128 + kc + c;   // row stride 1024 bf16 = 128 uint4
            su4[(SAH >> 2) + r * 9 + c] = pAh[go];
            su4[(SAL >> 2) + r * 9 + c] = pAl[go];
        }
        for (int idx = tid; idx < 512; idx += 256) {
            const int r = idx >> 3, c = idx & 7;
            const size_t go = (size_t)r * 128 + kc + c;
            su4[(SBH >> 2) + r * 9 + c] = pBh[go];
            su4[(SBL >> 2) + r * 9 + c] = pBl[go];
        }
        __syncthreads();
        mma_tile(su, SAH, SAL, SBH, SBL, wp * 16, g, t, c8);
        __syncthreads();
    }

    if (mode == 0) {
        const int part = n0 >> 10;          // 0=q,1=k,2=v (64-tile never crosses)
        const int b = m0 >> 11;
        const int mloc = m0 & (N_ - 1);
        const int hh = (n0 & 1023) >> 6;
        const int bh = b * H_ + hh;
        if (part < 2) {
            const float SCp = (part == 0) ? 0.03125f : 1.0f;
            unsigned* uh = reinterpret_cast<unsigned*>(part == 0 ? g_qh : g_kh);
            unsigned* ul = reinterpret_cast<unsigned*>(part == 0 ? g_ql : g_kl);
#pragma unroll
            for (int nt = 0; nt < 8; nt++) {
                const int d = nt * 8 + 2 * t;
                unsigned hi, lo;
                split2(c8[nt][0] * SCp, c8[nt][1] * SCp, hi, lo);
                const size_t o0 = (((size_t)bh * N_ + mloc + r0) * D_ + d) >> 1;
                uh[o0] = hi; ul[o0] = lo;
                split2(c8[nt][2] * SCp, c8[nt][3] * SCp, hi, lo);
                const size_t o1 = (((size_t)bh * N_ + mloc + r1) * D_ + d) >> 1;
                uh[o1] = hi; ul[o1] = lo;
            }
        } else {
            // v: transpose through smem (d-major, stride 132 -> conflict-free writes)
            float* vt = reinterpret_cast<float*>(su);
#pragma unroll
            for (int nt = 0; nt < 8; nt++) {
                const int d = nt * 8 + 2 * t;
                vt[(d + 0) * 132 + r0] = c8[nt][0];
                vt[(d + 1) * 132 + r0] = c8[nt][1];
                vt[(d + 0) * 132 + r1] = c8[nt][2];
                vt[(d + 1) * 132 + r1] = c8[nt][3];
            }
            __syncthreads();
            for (int u = tid; u < 1024; u += 256) {
                const int d = u >> 4, cc = (u & 15) * 8;
                unsigned h4[4], l4[4];
#pragma unroll
                for (int p = 0; p < 4; p++)
                    split2(vt[d * 132 + cc + 2 * p], vt[d * 132 + cc + 2 * p + 1],
                           h4[p], l4[p]);
                const size_t off = (((size_t)bh * D_ + d) * N_ + mloc + cc) >> 3;
                reinterpret_cast<uint4*>(g_vh)[off] = make_uint4(h4[0], h4[1], h4[2], h4[3]);
                reinterpret_cast<uint4*>(g_vl)[off] = make_uint4(l4[0], l4[1], l4[2], l4[3]);
            }
        }
    } else {
#pragma unroll
        for (int nt = 0; nt < 8; nt++) {
            const int n = n0 + nt * 8 + 2 * t;
            *reinterpret_cast<float2*>(&Cout[(size_t)(m0 + r0) * DIM_ + n]) =
                make_float2(c8[nt][0], c8[nt][1]);
            *reinterpret_cast<float2*>(&Cout[(size_t)(m0 + r1) * DIM_ + n]) =
                make_float2(c8[nt][2], c8[nt][3]);
        }
    }
}

// ---------------- tensor-core segment attention ----------------
#define SQH 0
#define SQL 4608
#define SKH 9216
#define SKL 11520
#define SVH 13824
#define SVL 16128
#define SWH 18432
#define SWL 23040

#define ACCSEG(DS, SG, E)                                                      \
    { if ((SG) == 0) DS[0] += (E); else if ((SG) == 1) DS[1] += (E);           \
      else if ((SG) == 2) DS[2] += (E); else DS[3] += (E); }

__global__ __launch_bounds__(256, 2) void attn_mma(const int* __restrict__ mask) {
    extern __shared__ unsigned su[];
    float* dshf = reinterpret_cast<float*>(su + 27648);
    float* invf = reinterpret_cast<float*>(su + 28160);
    uint4* su4 = reinterpret_cast<uint4*>(su);

    const int b = blockIdx.z, h = blockIdx.x;
    const int i0 = blockIdx.y * 128;
    const int bh = b * H_ + h;
    const int tid = threadIdx.x;
    const int lane = tid & 31, wp = tid >> 5;
    const int g = lane >> 2, t = lane & 3;
    const int r0 = wp * 16 + g, r1 = r0 + 8;
    const int* mrow = mask + (size_t)b * N_ * N_ + (size_t)i0 * N_;

    {
        const uint4* gqh = reinterpret_cast<const uint4*>(g_qh + ((size_t)bh * N_ + i0) * D_);
        const uint4* gql = reinterpret_cast<const uint4*>(g_ql + ((size_t)bh * N_ + i0) * D_);
        for (int idx = tid; idx < 1024; idx += 256) {
            const int r = idx >> 3, c = idx & 7;
            su4[(SQH >> 2) + r * 9 + c] = gqh[idx];
            su4[(SQL >> 2) + r * 9 + c] = gql[idx];
        }
    }

    // PASS 1: denominators
    float ds0[4] = {0.f, 0.f, 0.f, 0.f}, ds1[4] = {0.f, 0.f, 0.f, 0.f};
    for (int j0 = 0; j0 < N_; j0 += 64) {
        const uint4* gkh = reinterpret_cast<const uint4*>(g_kh + ((size_t)bh * N_ + j0) * D_);
        const uint4* gkl = reinterpret_cast<const uint4*>(g_kl + ((size_t)bh * N_ + j0) * D_);
        for (int idx = tid; idx < 512; idx += 256) {
            const int r = idx >> 3, c = idx & 7;
            su4[(SKH >> 2) + r * 9 + c] = gkh[idx];
            su4[(SKL >> 2) + r * 9 + c] = gkl[idx];
        }
        __syncthreads();
        float c8[8][4] = {};
        mma_tile(su, SQH, SQL, SKH, SKL, wp * 16, g, t, c8);
#pragma unroll
        for (int nt = 0; nt < 8; nt++) {
            const int jc = j0 + nt * 8 + 2 * t;
            const int2 m0 = *reinterpret_cast<const int2*>(&mrow[(size_t)r0 * N_ + jc]);
            const int2 m1 = *reinterpret_cast<const int2*>(&mrow[(size_t)r1 * N_ + jc]);
            const float e0 = __expf(c8[nt][0]), e1 = __expf(c8[nt][1]);
            const float e2 = __expf(c8[nt][2]), e3 = __expf(c8[nt][3]);
            ACCSEG(ds0, m0.x, e0) ACCSEG(ds0, m0.y, e1)
            ACCSEG(ds1, m1.x, e2) ACCSEG(ds1, m1.y, e3)
        }
        __syncthreads();
    }
#pragma unroll
    for (int s = 0; s < 4; s++) {
        float v0 = ds0[s], v1 = ds1[s];
        v0 += __shfl_xor_sync(0xffffffffu, v0, 1);
        v0 += __shfl_xor_sync(0xffffffffu, v0, 2);
        v1 += __shfl_xor_sync(0xffffffffu, v1, 1);
        v1 += __shfl_xor_sync(0xffffffffu, v1, 2);
        if (t == 0) { dshf[r0 * 4 + s] = v0; dshf[r1 * 4 + s] = v1; }
    }
    __syncthreads();
    for (int idx = tid; idx < 512; idx += 256) {
        const float dv = dshf[idx];
        invf[idx] = (dv == 0.0f) ? 1.0f : 1.0f / dv;
    }
    __syncthreads();

    // PASS 2
    float o8[8][4] = {};
    for (int j0 = 0; j0 < N_; j0 += 64) {
        const uint4* gkh = reinterpret_cast<const uint4*>(g_kh + ((size_t)bh * N_ + j0) * D_);
        const uint4* gkl = reinterpret_cast<const uint4*>(g_kl + ((size_t)bh * N_ + j0) * D_);
        const uint4* gvh = reinterpret_cast<const uint4*>(g_vh);
        const uint4* gvl = reinterpret_cast<const uint4*>(g_vl);
        for (int idx = tid; idx < 512; idx += 256) {
            const int r = idx >> 3, c = idx & 7;
            su4[(SKH >> 2) + r * 9 + c] = gkh[idx];
            su4[(SKL >> 2) + r * 9 + c] = gkl[idx];
            const size_t vi = ((size_t)bh * D_ + r) * 256 + (j0 >> 3) + c;
            su4[(SVH >> 2) + r * 9 + c] = gvh[vi];
            su4[(SVL >> 2) + r * 9 + c] = gvl[vi];
        }
        __syncthreads();
        float c8[8][4] = {};
        mma_tile(su, SQH, SQL, SKH, SKL, wp * 16, g, t, c8);
#pragma unroll
        for (int nt = 0; nt < 8; nt++) {
            const int jc = j0 + nt * 8 + 2 * t;
            const int2 m0 = *reinterpret_cast<const int2*>(&mrow[(size_t)r0 * N_ + jc]);
            const int2 m1 = *reinterpret_cast<const int2*>(&mrow[(size_t)r1 * N_ + jc]);
            const float w00 = __expf(c8[nt][0]) * invf[r0 * 4 + m0.x];
            const float w01 = __expf(c8[nt][1]) * invf[r0 * 4 + m0.y];
            const float w10 = __expf(c8[nt][2]) * invf[r1 * 4 + m1.x];
            const float w11 = __expf(c8[nt][3]) * invf[r1 * 4 + m1.y];
            unsigned hi, lo;
            split2(w00, w01, hi, lo);
            su[SWH + r0 * 36 + nt * 4 + t] = hi;
            su[SWL + r0 * 36 + nt * 4 + t] = lo;
            split2(w10, w11, hi, lo);
            su[SWH + r1 * 36 + nt * 4 + t] = hi;
            su[SWL + r1 * 36 + nt * 4 + t] = lo;
        }
        __syncwarp();
        mma_tile(su, SWH, SWL, SVH, SVL, wp * 16, g, t, o8);
        __syncthreads();
    }

    // store O as split bf16
    {
        unsigned* ah = reinterpret_cast<unsigned*>(g_ah);
        unsigned* al = reinterpret_cast<unsigned*>(g_al);
#pragma unroll
        for (int nt = 0; nt < 8; nt++) {
            const int d = h * 64 + nt * 8 + 2 * t;
            unsigned hi, lo;
            split2(o8[nt][0], o8[nt][1], hi, lo);
            const size_t o0 = ((size_t)(b * N_ + i0 + r0) * DIM_ + d) >> 1;
            ah[o0] = hi; al[o0] = lo;
            split2(o8[nt][2], o8[nt][3], hi, lo);
            const size_t o1 = ((size_t)(b * N_ + i0 + r1) * DIM_ + d) >> 1;
            ah[o1] = hi; al[o1] = lo;
        }
    }
}

// ---------------------------------------------------------------------------
extern "C" void kernel_launch(void* const* d_in, const int* in_sizes, int n_in,
                              void* d_out, int out_size) {
    const float* features = (const float*)d_in[0];
    const int*   mask     = (const int*)d_in[1];
    const float* W_qkv    = (const float*)d_in[2];
    const float* W_out    = (const float*)d_in[3];
    float* out = (float*)d_out;

    cudaFuncSetAttribute(attn_mma, cudaFuncAttributeMaxDynamicSharedMemorySize, 114688);
    cudaFuncSetAttribute(mma_gemm, cudaFuncAttributeMaxDynamicSharedMemorySize, 55296);

    __nv_bfloat16 *fh, *fl, *wqh, *wql, *woh, *wol;
    cudaGetSymbolAddress((void**)&fh, g_fh);   cudaGetSymbolAddress((void**)&fl, g_fl);
    cudaGetSymbolAddress((void**)&wqh, g_wqh); cudaGetSymbolAddress((void**)&wql, g_wql);
    cudaGetSymbolAddress((void**)&woh, g_woh); cudaGetSymbolAddress((void**)&wol, g_wol);
    __nv_bfloat16 *ah, *al;
    cudaGetSymbolAddress((void**)&ah, g_ah);   cudaGetSymbolAddress((void**)&al, g_al);

    // split features + weights
    split_f32<<<(M_ * DIM_ / 2 + 255) / 256, 256>>>(features, fh, fl, M_ * DIM_ / 2);
    tsplit_w<<<dim3(3 * DIM_ / 32, DIM_ / 32), 256>>>(W_qkv, wqh, wql, DIM_, 3 * DIM_);
    tsplit_w<<<dim3(DIM_ / 32, DIM_ / 32), 256>>>(W_out, woh, wol, DIM_, DIM_);

    // qkv projection (tensor cores) -> split q/k/v
    mma_gemm<<<dim3(3 * DIM_ / 64, M_ / 128), 256, 55296>>>(fh, fl, wqh, wql, nullptr, 0);
    // fused masked-segment attention (tensor cores) -> split g_ah/g_al
    attn_mma<<<dim3(H_, N_ / 128, B_), 256, 114688>>>(mask);
    // out projection (tensor cores) -> fp32 out
    mma_gemm<<<dim3(DIM_ / 64, M_ / 128), 256, 55296>>>(ah, al, woh, wol, out, 1);
}

// round 7
// speedup vs baseline: 2.1181x; 1.0796x over previous
#include <cuda_runtime.h>
#include <cuda_bf16.h>

#define B_   2
#define N_   2048
#define DIM_ 1024
#define H_   16
#define D_   64
#define BH_  (B_ * H_)
#define M_   (B_ * N_)

// ---- device scratch (allocation-free rule) ----
__device__ __nv_bfloat16 g_fh[(size_t)M_ * DIM_];
__device__ __nv_bfloat16 g_fl[(size_t)M_ * DIM_];
__device__ __nv_bfloat16 g_wqh[(size_t)3 * DIM_ * DIM_];
__device__ __nv_bfloat16 g_wql[(size_t)3 * DIM_ * DIM_];
__device__ __nv_bfloat16 g_woh[(size_t)DIM_ * DIM_];
__device__ __nv_bfloat16 g_wol[(size_t)DIM_ * DIM_];
__device__ __nv_bfloat16 g_qh[(size_t)BH_ * N_ * D_];
__device__ __nv_bfloat16 g_ql[(size_t)BH_ * N_ * D_];
__device__ __nv_bfloat16 g_kh[(size_t)BH_ * N_ * D_];
__device__ __nv_bfloat16 g_kl[(size_t)BH_ * N_ * D_];
__device__ __nv_bfloat16 g_vh[(size_t)BH_ * D_ * N_];
__device__ __nv_bfloat16 g_vl[(size_t)BH_ * D_ * N_];
__device__ __nv_bfloat16 g_ah[(size_t)M_ * DIM_];
__device__ __nv_bfloat16 g_al[(size_t)M_ * DIM_];
__device__ float g_e[(size_t)BH_ * N_ * N_];           // exp(scores), warp-packed

__device__ __forceinline__ unsigned b2u(__nv_bfloat162 v) {
    return *reinterpret_cast<unsigned*>(&v);
}
__device__ __forceinline__ void split2(float x0, float x1, unsigned& hi, unsigned& lo) {
    __nv_bfloat162 h2 = __floats2bfloat162_rn(x0, x1);
    __nv_bfloat162 l2 = __floats2bfloat162_rn(x0 - __bfloat162float(h2.x),
                                              x1 - __bfloat162float(h2.y));
    hi = b2u(h2); lo = b2u(l2);
}

__device__ __forceinline__ void mma16816(float* c, unsigned a0, unsigned a1,
                                         unsigned a2, unsigned a3,
                                         unsigned b0, unsigned b1) {
    asm("mma.sync.aligned.m16n8k16.row.col.f32.bf16.bf16.f32 "
        "{%0,%1,%2,%3},{%4,%5,%6,%7},{%8,%9},{%0,%1,%2,%3};\n"
        : "+f"(c[0]), "+f"(c[1]), "+f"(c[2]), "+f"(c[3])
        : "r"(a0), "r"(a1), "r"(a2), "r"(a3), "r"(b0), "r"(b1));
}

__device__ __forceinline__ void cpa16(unsigned dst, const void* src) {
    asm volatile("cp.async.cg.shared.global [%0], [%1], 16;\n" :: "r"(dst), "l"(src));
}
__device__ __forceinline__ void cp_commit() { asm volatile("cp.async.commit_group;\n"); }
__device__ __forceinline__ void cp_wait1() { asm volatile("cp.async.wait_group 1;\n"); }
__device__ __forceinline__ void cp_wait0() { asm volatile("cp.async.wait_group 0;\n"); }

// m16(rows arow+g/+8) x n64 x k64, hi/lo split (3 products), stride 36 words.
__device__ __forceinline__ void mma_tile(const unsigned* su, int AH, int AL,
                                         int BHo, int BLo, int arow, int g, int t,
                                         float c[8][4]) {
#pragma unroll
    for (int ks = 0; ks < 4; ks++) {
        const int ar = (arow + g) * 36 + ks * 8 + t;
        unsigned ah0 = su[AH + ar],       ah1 = su[AH + ar + 288];
        unsigned ah2 = su[AH + ar + 4],   ah3 = su[AH + ar + 292];
        unsigned al0 = su[AL + ar],       al1 = su[AL + ar + 288];
        unsigned al2 = su[AL + ar + 4],   al3 = su[AL + ar + 292];
#pragma unroll
        for (int nt = 0; nt < 8; nt++) {
            const int br = (nt * 8 + g) * 36 + ks * 8 + t;
            unsigned bh0 = su[BHo + br], bh1 = su[BHo + br + 4];
            unsigned bl0 = su[BLo + br], bl1 = su[BLo + br + 4];
            mma16816(c[nt], ah0, ah1, ah2, ah3, bh0, bh1);
            mma16816(c[nt], ah0, ah1, ah2, ah3, bl0, bl1);
            mma16816(c[nt], al0, al1, al2, al3, bh0, bh1);
        }
    }
}

// ---------------- preprocess: splits ----------------
__global__ __launch_bounds__(256) void split_f32(const float* __restrict__ src,
                                                 __nv_bfloat16* __restrict__ dh,
                                                 __nv_bfloat16* __restrict__ dl,
                                                 int n2) {
    int i = blockIdx.x * 256 + threadIdx.x;
    if (i < n2) {
        float2 v = reinterpret_cast<const float2*>(src)[i];
        unsigned hi, lo; split2(v.x, v.y, hi, lo);
        reinterpret_cast<unsigned*>(dh)[i] = hi;
        reinterpret_cast<unsigned*>(dl)[i] = lo;
    }
}

__global__ __launch_bounds__(256) void tsplit_w(const float* __restrict__ W,
                                                __nv_bfloat16* __restrict__ dh,
                                                __nv_bfloat16* __restrict__ dl,
                                                int K, int NB) {
    __shared__ float tile[32][33];
    const int n0 = blockIdx.x * 32, k0 = blockIdx.y * 32;
    const int tx = threadIdx.x & 31, ty = threadIdx.x >> 5;
    for (int r = ty; r < 32; r += 8)
        tile[r][tx] = W[(size_t)(k0 + r) * NB + n0 + tx];
    __syncthreads();
    for (int u = threadIdx.x; u < 512; u += 256) {
        const int rr = u >> 4, c = (u & 15) * 2;
        unsigned hi, lo; split2(tile[c][rr], tile[c + 1][rr], hi, lo);
        const size_t off = ((size_t)(n0 + rr) * K + k0 + c) >> 1;
        reinterpret_cast<unsigned*>(dh)[off] = hi;
        reinterpret_cast<unsigned*>(dl)[off] = lo;
    }
}

// ---------------- tensor-core GEMM: 128m x 64n, K=1024, cp.async 2-stage ----
// stage layout (words): AH 0, AL 4608, BH 9216, BL 11520; stage stride 13824
#define SAH 0
#define SAL 4608
#define SBH 9216
#define SBL 11520
#define GSTG 13824

__global__ __launch_bounds__(256, 2) void mma_gemm(
    const __nv_bfloat16* __restrict__ Ah, const __nv_bfloat16* __restrict__ Al,
    const __nv_bfloat16* __restrict__ Bh, const __nv_bfloat16* __restrict__ Bl,
    float* __restrict__ Cout, int mode) {
    extern __shared__ unsigned su[];
    const unsigned sbase = (unsigned)__cvta_generic_to_shared(su);
    const int K = 1024;
    const int m0 = blockIdx.y * 128, n0 = blockIdx.x * 64;
    const int tid = threadIdx.x, lane = tid & 31, wp = tid >> 5;
    const int g = lane >> 2, t = lane & 3;
    const int r0 = wp * 16 + g, r1 = r0 + 8;

    const uint4* pAh = reinterpret_cast<const uint4*>(Ah + (size_t)m0 * K);
    const uint4* pAl = reinterpret_cast<const uint4*>(Al + (size_t)m0 * K);
    const uint4* pBh = reinterpret_cast<const uint4*>(Bh + (size_t)n0 * K);
    const uint4* pBl = reinterpret_cast<const uint4*>(Bl + (size_t)n0 * K);

    float c8[8][4] = {};

#define GLOAD(ST, K0)                                                          \
    {                                                                          \
        const int kc = (K0) >> 3;                                              \
        const unsigned base = sbase + (ST) * (GSTG * 4);                       \
        for (int idx = tid; idx < 2048; idx += 256) {                          \
            const int half = idx >> 10, r = (idx & 1023) >> 3, c = idx & 7;    \
            cpa16(base + (half ? SAL : SAH) * 4 + (r * 9 + c) * 16,            \
                  (half ? pAl : pAh) + (size_t)r * 128 + kc + c);              \
        }                                                                      \
        for (int idx = tid; idx < 1024; idx += 256) {                          \
            const int half = idx >> 9, r = (idx & 511) >> 3, c = idx & 7;      \
            cpa16(base + (half ? SBL : SBH) * 4 + (r * 9 + c) * 16,            \
                  (half ? pBl : pBh) + (size_t)r * 128 + kc + c);              \
        }                                                                      \
        cp_commit();                                                           \
    }

    GLOAD(0, 0)
    for (int it = 0; it < 16; it++) {
        if (it + 1 < 16) { GLOAD((it + 1) & 1, (it + 1) * 64) cp_wait1(); }
        else cp_wait0();
        __syncthreads();
        mma_tile(su + (it & 1) * GSTG, SAH, SAL, SBH, SBL, wp * 16, g, t, c8);
        __syncthreads();
    }
#undef GLOAD

    if (mode == 0) {
        const int part = n0 >> 10;
        const int b = m0 >> 11;
        const int mloc = m0 & (N_ - 1);
        const int hh = (n0 & 1023) >> 6;
        const int bh = b * H_ + hh;
        if (part < 2) {
            const float SCp = (part == 0) ? 0.03125f : 1.0f;
            unsigned* uh = reinterpret_cast<unsigned*>(part == 0 ? g_qh : g_kh);
            unsigned* ul = reinterpret_cast<unsigned*>(part == 0 ? g_ql : g_kl);
#pragma unroll
            for (int nt = 0; nt < 8; nt++) {
                const int d = nt * 8 + 2 * t;
                unsigned hi, lo;
                split2(c8[nt][0] * SCp, c8[nt][1] * SCp, hi, lo);
                const size_t o0 = (((size_t)bh * N_ + mloc + r0) * D_ + d) >> 1;
                uh[o0] = hi; ul[o0] = lo;
                split2(c8[nt][2] * SCp, c8[nt][3] * SCp, hi, lo);
                const size_t o1 = (((size_t)bh * N_ + mloc + r1) * D_ + d) >> 1;
                uh[o1] = hi; ul[o1] = lo;
            }
        } else {
            float* vt = reinterpret_cast<float*>(su);
#pragma unroll
            for (int nt = 0; nt < 8; nt++) {
                const int d = nt * 8 + 2 * t;
                vt[(d + 0) * 132 + r0] = c8[nt][0];
                vt[(d + 1) * 132 + r0] = c8[nt][1];
                vt[(d + 0) * 132 + r1] = c8[nt][2];
                vt[(d + 1) * 132 + r1] = c8[nt][3];
            }
            __syncthreads();
            for (int u = tid; u < 1024; u += 256) {
                const int d = u >> 4, cc = (u & 15) * 8;
                unsigned h4[4], l4[4];
#pragma unroll
                for (int p = 0; p < 4; p++)
                    split2(vt[d * 132 + cc + 2 * p], vt[d * 132 + cc + 2 * p + 1],
                           h4[p], l4[p]);
                const size_t off = (((size_t)bh * D_ + d) * N_ + mloc + cc) >> 3;
                reinterpret_cast<uint4*>(g_vh)[off] = make_uint4(h4[0], h4[1], h4[2], h4[3]);
                reinterpret_cast<uint4*>(g_vl)[off] = make_uint4(l4[0], l4[1], l4[2], l4[3]);
            }
        }
    } else {
#pragma unroll
        for (int nt = 0; nt < 8; nt++) {
            const int n = n0 + nt * 8 + 2 * t;
            *reinterpret_cast<float2*>(&Cout[(size_t)(m0 + r0) * DIM_ + n]) =
                make_float2(c8[nt][0], c8[nt][1]);
            *reinterpret_cast<float2*>(&Cout[(size_t)(m0 + r1) * DIM_ + n]) =
                make_float2(c8[nt][2], c8[nt][3]);
        }
    }
}

// ---------------- tensor-core segment attention ----------------
// smem words: QH 0, QL 4608; stages: ST(s)=9216+s*4608 (XH +0, XL +2304);
// WH 18432, WL 23040; dsh 27648; inv 28160; total 28672 w = 114688 B
#define SQH 0
#define SQL 4608
#define SWH 18432
#define SWL 23040

#define ACCSEG(DS, SG, E)                                                      \
    { if ((SG) == 0) DS[0] += (E); else if ((SG) == 1) DS[1] += (E);           \
      else if ((SG) == 2) DS[2] += (E); else DS[3] += (E); }

__global__ __launch_bounds__(256, 2) void attn_mma(const int* __restrict__ mask) {
    extern __shared__ unsigned su[];
    const unsigned sbase = (unsigned)__cvta_generic_to_shared(su);
    float* dshf = reinterpret_cast<float*>(su + 27648);
    float* invf = reinterpret_cast<float*>(su + 28160);
    uint4* su4 = reinterpret_cast<uint4*>(su);

    const int b = blockIdx.z, h = blockIdx.x;
    const int i0 = blockIdx.y * 128;
    const int bh = b * H_ + h;
    const int tid = threadIdx.x;
    const int lane = tid & 31, wp = tid >> 5;
    const int g = lane >> 2, t = lane & 3;
    const int r0 = wp * 16 + g, r1 = r0 + 8;
    const int* mrow = mask + (size_t)b * N_ * N_ + (size_t)i0 * N_;
    float* eblk = g_e + (((size_t)bh * (N_ / 128) + blockIdx.y) * (N_ / 64)) * 8192;

    // load Q tile
    {
        const uint4* gqh = reinterpret_cast<const uint4*>(g_qh + ((size_t)bh * N_ + i0) * D_);
        const uint4* gql = reinterpret_cast<const uint4*>(g_ql + ((size_t)bh * N_ + i0) * D_);
        for (int idx = tid; idx < 1024; idx += 256) {
            const int r = idx >> 3, c = idx & 7;
            su4[(SQH >> 2) + r * 9 + c] = gqh[idx];
            su4[(SQL >> 2) + r * 9 + c] = gql[idx];
        }
    }

    const uint4* gkh = reinterpret_cast<const uint4*>(g_kh + (size_t)bh * N_ * D_);
    const uint4* gkl = reinterpret_cast<const uint4*>(g_kl + (size_t)bh * N_ * D_);
    const uint4* gvh = reinterpret_cast<const uint4*>(g_vh + (size_t)bh * D_ * N_);
    const uint4* gvl = reinterpret_cast<const uint4*>(g_vl + (size_t)bh * D_ * N_);

#define LOADK(ST, JT)                                                          \
    {                                                                          \
        const unsigned base = sbase + (9216 + (ST) * 4608) * 4;                \
        const int jr = (JT) * 512;  /* row jt*64, 8 uint4 per row */           \
        for (int idx = tid; idx < 1024; idx += 256) {                          \
            const int half = idx >> 9, r = (idx & 511) >> 3, c = idx & 7;      \
            cpa16(base + half * 9216 + (r * 9 + c) * 16,                       \
                  (half ? gkl : gkh) + jr + (size_t)r * 8 + c);                \
        }                                                                      \
        cp_commit();                                                           \
    }
#define LOADV(ST, JT)                                                          \
    {                                                                          \
        const unsigned base = sbase + (9216 + (ST) * 4608) * 4;                \
        const int jc = (JT) * 8;  /* uint4 col offset within 2048-wide row */  \
        for (int idx = tid; idx < 1024; idx += 256) {                          \
            const int half = idx >> 9, r = (idx & 511) >> 3, c = idx & 7;      \
            cpa16(base + half * 9216 + (r * 9 + c) * 16,                       \
                  (half ? gvl : gvh) + (size_t)r * 256 + jc + c);              \
        }                                                                      \
        cp_commit();                                                           \
    }

    // ---------------- PASS 1: denominators + e store ----------------
    float ds0[4] = {0.f, 0.f, 0.f, 0.f}, ds1[4] = {0.f, 0.f, 0.f, 0.f};
    LOADK(0, 0)
    for (int jt = 0; jt < 32; jt++) {
        if (jt + 1 < 32) { LOADK((jt + 1) & 1, jt + 1) cp_wait1(); }
        else cp_wait0();
        __syncthreads();
        const int koff = 9216 + (jt & 1) * 4608;
        float c8[8][4] = {};
        mma_tile(su, SQH, SQL, koff, koff + 2304, wp * 16, g, t, c8);
        __syncthreads();
        float* ew = eblk + ((size_t)jt * 8 + wp) * 1024;
        const int j0 = jt * 64;
#pragma unroll
        for (int nt = 0; nt < 8; nt++) {
            const int jc = j0 + nt * 8 + 2 * t;
            const int2 m0 = *reinterpret_cast<const int2*>(&mrow[(size_t)r0 * N_ + jc]);
            const int2 m1 = *reinterpret_cast<const int2*>(&mrow[(size_t)r1 * N_ + jc]);
            const float e0 = __expf(c8[nt][0]), e1 = __expf(c8[nt][1]);
            const float e2 = __expf(c8[nt][2]), e3 = __expf(c8[nt][3]);
            ACCSEG(ds0, m0.x, e0) ACCSEG(ds0, m0.y, e1)
            ACCSEG(ds1, m1.x, e2) ACCSEG(ds1, m1.y, e3)
            *reinterpret_cast<float2*>(&ew[nt * 128 + g * 8 + 2 * t]) =
                make_float2(e0, e1);
            *reinterpret_cast<float2*>(&ew[nt * 128 + 64 + g * 8 + 2 * t]) =
                make_float2(e2, e3);
        }
    }
#pragma unroll
    for (int s = 0; s < 4; s++) {
        float v0 = ds0[s], v1 = ds1[s];
        v0 += __shfl_xor_sync(0xffffffffu, v0, 1);
        v0 += __shfl_xor_sync(0xffffffffu, v0, 2);
        v1 += __shfl_xor_sync(0xffffffffu, v1, 1);
        v1 += __shfl_xor_sync(0xffffffffu, v1, 2);
        if (t == 0) { dshf[r0 * 4 + s] = v0; dshf[r1 * 4 + s] = v1; }
    }
    __syncthreads();
    for (int idx = tid; idx < 512; idx += 256) {
        const float dv = dshf[idx];
        invf[idx] = (dv == 0.0f) ? 1.0f : 1.0f / dv;
    }
    __syncthreads();

    // ---------------- PASS 2: w = e*invd -> O += w @ V ----------------
    float o8[8][4] = {};
    LOADV(0, 0)
    for (int jt = 0; jt < 32; jt++) {
        if (jt + 1 < 32) LOADV((jt + 1) & 1, jt + 1)
        // build w tile from stored e (independent of V arrival)
        const float* ew = eblk + ((size_t)jt * 8 + wp) * 1024;
        const int j0 = jt * 64;
        const float iv0[4] = {invf[r0 * 4 + 0], invf[r0 * 4 + 1],
                              invf[r0 * 4 + 2], invf[r0 * 4 + 3]};
        const float iv1[4] = {invf[r1 * 4 + 0], invf[r1 * 4 + 1],
                              invf[r1 * 4 + 2], invf[r1 * 4 + 3]};
#pragma unroll
        for (int nt = 0; nt < 8; nt++) {
            const int jc = j0 + nt * 8 + 2 * t;
            const int2 m0 = *reinterpret_cast<const int2*>(&mrow[(size_t)r0 * N_ + jc]);
            const int2 m1 = *reinterpret_cast<const int2*>(&mrow[(size_t)r1 * N_ + jc]);
            const float2 eA = *reinterpret_cast<const float2*>(&ew[nt * 128 + g * 8 + 2 * t]);
            const float2 eB = *reinterpret_cast<const float2*>(&ew[nt * 128 + 64 + g * 8 + 2 * t]);
            unsigned hi, lo;
            split2(eA.x * iv0[m0.x], eA.y * iv0[m0.y], hi, lo);
            su[SWH + r0 * 36 + nt * 4 + t] = hi;
            su[SWL + r0 * 36 + nt * 4 + t] = lo;
            split2(eB.x * iv1[m1.x], eB.y * iv1[m1.y], hi, lo);
            su[SWH + r1 * 36 + nt * 4 + t] = hi;
            su[SWL + r1 * 36 + nt * 4 + t] = lo;
        }
        if (jt + 1 < 32) cp_wait1(); else cp_wait0();
        __syncthreads();
        const int voff = 9216 + (jt & 1) * 4608;
        mma_tile(su, SWH, SWL, voff, voff + 2304, wp * 16, g, t, o8);
        __syncthreads();
    }
#undef LOADK
#undef LOADV

    // store O as split bf16
    {
        unsigned* ah = reinterpret_cast<unsigned*>(g_ah);
        unsigned* al = reinterpret_cast<unsigned*>(g_al);
#pragma unroll
        for (int nt = 0; nt < 8; nt++) {
            const int d = h * 64 + nt * 8 + 2 * t;
            unsigned hi, lo;
            split2(o8[nt][0], o8[nt][1], hi, lo);
            const size_t o0 = ((size_t)(b * N_ + i0 + r0) * DIM_ + d) >> 1;
            ah[o0] = hi; al[o0] = lo;
            split2(o8[nt][2], o8[nt][3], hi, lo);
            const size_t o1 = ((size_t)(b * N_ + i0 + r1) * DIM_ + d) >> 1;
            ah[o1] = hi; al[o1] = lo;
        }
    }
}

// ---------------------------------------------------------------------------
extern "C" void kernel_launch(void* const* d_in, const int* in_sizes, int n_in,
                              void* d_out, int out_size) {
    const float* features = (const float*)d_in[0];
    const int*   mask     = (const int*)d_in[1];
    const float* W_qkv    = (const float*)d_in[2];
    const float* W_out    = (const float*)d_in[3];
    float* out = (float*)d_out;

    cudaFuncSetAttribute(attn_mma, cudaFuncAttributeMaxDynamicSharedMemorySize, 114688);
    cudaFuncSetAttribute(mma_gemm, cudaFuncAttributeMaxDynamicSharedMemorySize, 110592);

    __nv_bfloat16 *fh, *fl, *wqh, *wql, *woh, *wol, *ah, *al;
    cudaGetSymbolAddress((void**)&fh, g_fh);   cudaGetSymbolAddress((void**)&fl, g_fl);
    cudaGetSymbolAddress((void**)&wqh, g_wqh); cudaGetSymbolAddress((void**)&wql, g_wql);
    cudaGetSymbolAddress((void**)&woh, g_woh); cudaGetSymbolAddress((void**)&wol, g_wol);
    cudaGetSymbolAddress((void**)&ah, g_ah);   cudaGetSymbolAddress((void**)&al, g_al);

    split_f32<<<(M_ * DIM_ / 2 + 255) / 256, 256>>>(features, fh, fl, M_ * DIM_ / 2);
    tsplit_w<<<dim3(3 * DIM_ / 32, DIM_ / 32), 256>>>(W_qkv, wqh, wql, DIM_, 3 * DIM_);
    tsplit_w<<<dim3(DIM_ / 32, DIM_ / 32), 256>>>(W_out, woh, wol, DIM_, DIM_);

    mma_gemm<<<dim3(3 * DIM_ / 64, M_ / 128), 256, 110592>>>(fh, fl, wqh, wql, nullptr, 0);
    attn_mma<<<dim3(H_, N_ / 128, B_), 256, 114688>>>(mask);
    mma_gemm<<<dim3(DIM_ / 64, M_ / 128), 256, 110592>>>(ah, al, woh, wol, out, 1);
}

// round 8
// speedup vs baseline: 2.1713x; 1.0251x over previous
#include <cuda_runtime.h>
#include <cuda_bf16.h>

#define B_   2
#define N_   2048
#define DIM_ 1024
#define H_   16
#define D_   64
#define BH_  (B_ * H_)
#define M_   (B_ * N_)

// ---- device scratch (allocation-free rule) ----
__device__ __nv_bfloat16 g_fh[(size_t)M_ * DIM_];
__device__ __nv_bfloat16 g_fl[(size_t)M_ * DIM_];
__device__ __nv_bfloat16 g_wqh[(size_t)3 * DIM_ * DIM_];
__device__ __nv_bfloat16 g_wql[(size_t)3 * DIM_ * DIM_];
__device__ __nv_bfloat16 g_woh[(size_t)DIM_ * DIM_];
__device__ __nv_bfloat16 g_wol[(size_t)DIM_ * DIM_];
__device__ __nv_bfloat16 g_qh[(size_t)BH_ * N_ * D_];
__device__ __nv_bfloat16 g_ql[(size_t)BH_ * N_ * D_];
__device__ __nv_bfloat16 g_kh[(size_t)BH_ * N_ * D_];
__device__ __nv_bfloat16 g_kl[(size_t)BH_ * N_ * D_];
__device__ __nv_bfloat16 g_vh[(size_t)BH_ * D_ * N_];
__device__ __nv_bfloat16 g_vl[(size_t)BH_ * D_ * N_];
__device__ __nv_bfloat16 g_ah[(size_t)M_ * DIM_];
__device__ __nv_bfloat16 g_al[(size_t)M_ * DIM_];
__device__ float g_e[(size_t)BH_ * N_ * N_];           // exp(scores), warp-packed

__device__ __forceinline__ unsigned b2u(__nv_bfloat162 v) {
    return *reinterpret_cast<unsigned*>(&v);
}
__device__ __forceinline__ void split2(float x0, float x1, unsigned& hi, unsigned& lo) {
    __nv_bfloat162 h2 = __floats2bfloat162_rn(x0, x1);
    __nv_bfloat162 l2 = __floats2bfloat162_rn(x0 - __bfloat162float(h2.x),
                                              x1 - __bfloat162float(h2.y));
    hi = b2u(h2); lo = b2u(l2);
}

__device__ __forceinline__ void mma16816(float* c, unsigned a0, unsigned a1,
                                         unsigned a2, unsigned a3,
                                         unsigned b0, unsigned b1) {
    asm("mma.sync.aligned.m16n8k16.row.col.f32.bf16.bf16.f32 "
        "{%0,%1,%2,%3},{%4,%5,%6,%7},{%8,%9},{%0,%1,%2,%3};\n"
        : "+f"(c[0]), "+f"(c[1]), "+f"(c[2]), "+f"(c[3])
        : "r"(a0), "r"(a1), "r"(a2), "r"(a3), "r"(b0), "r"(b1));
}

__device__ __forceinline__ void ldsm4(unsigned addr, unsigned& r0, unsigned& r1,
                                      unsigned& r2, unsigned& r3) {
    asm volatile("ldmatrix.sync.aligned.m8n8.x4.shared.b16 {%0,%1,%2,%3}, [%4];\n"
                 : "=r"(r0), "=r"(r1), "=r"(r2), "=r"(r3) : "r"(addr));
}

__device__ __forceinline__ void cpa16(unsigned dst, const void* src) {
    asm volatile("cp.async.cg.shared.global [%0], [%1], 16;\n" :: "r"(dst), "l"(src));
}
__device__ __forceinline__ void cp_commit() { asm volatile("cp.async.commit_group;\n"); }
__device__ __forceinline__ void cp_wait1() { asm volatile("cp.async.wait_group 1;\n"); }
__device__ __forceinline__ void cp_wait0() { asm volatile("cp.async.wait_group 0;\n"); }

// m16(rows arow+g/+8) x n64 x k64, hi/lo split (3 products), stride 36 words.
// All operand fragments fetched via ldmatrix.x4 (conflict-free with stride 36).
__device__ __forceinline__ void mma_tile(unsigned sb, int AH, int AL,
                                         int BHo, int BLo, int arow, int lane,
                                         float c[8][4]) {
    const int m = lane >> 3, r = lane & 7;
    // A: matrices (rows, rows+8) x (k0-7, k8-15)
    const unsigned pa = ((unsigned)(arow + (m & 1) * 8 + r) * 36 + (m >> 1) * 4) * 4;
    // B: matrices (n-group, n-group+1) x (k0-7, k8-15) per pair
    const unsigned pb = (((unsigned)((m >> 1) * 8 + r)) * 36 + (m & 1) * 4) * 4;
#pragma unroll
    for (int ks = 0; ks < 4; ks++) {
        unsigned ah0, ah1, ah2, ah3, al0, al1, al2, al3;
        ldsm4(sb + AH * 4 + pa + ks * 32, ah0, ah1, ah2, ah3);
        ldsm4(sb + AL * 4 + pa + ks * 32, al0, al1, al2, al3);
#pragma unroll
        for (int ntp = 0; ntp < 4; ntp++) {
            unsigned bh0, bh1, bh2, bh3, bl0, bl1, bl2, bl3;
            const unsigned bofs = pb + ntp * (16 * 36 * 4) + ks * 32;
            ldsm4(sb + BHo * 4 + bofs, bh0, bh1, bh2, bh3);
            ldsm4(sb + BLo * 4 + bofs, bl0, bl1, bl2, bl3);
            mma16816(c[2 * ntp + 0], ah0, ah1, ah2, ah3, bh0, bh1);
            mma16816(c[2 * ntp + 0], ah0, ah1, ah2, ah3, bl0, bl1);
            mma16816(c[2 * ntp + 0], al0, al1, al2, al3, bh0, bh1);
            mma16816(c[2 * ntp + 1], ah0, ah1, ah2, ah3, bh2, bh3);
            mma16816(c[2 * ntp + 1], ah0, ah1, ah2, ah3, bl2, bl3);
            mma16816(c[2 * ntp + 1], al0, al1, al2, al3, bh2, bh3);
        }
    }
}

// ---------------- preprocess: splits ----------------
__global__ __launch_bounds__(256) void split_f32(const float* __restrict__ src,
                                                 __nv_bfloat16* __restrict__ dh,
                                                 __nv_bfloat16* __restrict__ dl,
                                                 int n2) {
    int i = blockIdx.x * 256 + threadIdx.x;
    if (i < n2) {
        float2 v = reinterpret_cast<const float2*>(src)[i];
        unsigned hi, lo; split2(v.x, v.y, hi, lo);
        reinterpret_cast<unsigned*>(dh)[i] = hi;
        reinterpret_cast<unsigned*>(dl)[i] = lo;
    }
}

__global__ __launch_bounds__(256) void tsplit_w(const float* __restrict__ W,
                                                __nv_bfloat16* __restrict__ dh,
                                                __nv_bfloat16* __restrict__ dl,
                                                int K, int NB) {
    __shared__ float tile[32][33];
    const int n0 = blockIdx.x * 32, k0 = blockIdx.y * 32;
    const int tx = threadIdx.x & 31, ty = threadIdx.x >> 5;
    for (int r = ty; r < 32; r += 8)
        tile[r][tx] = W[(size_t)(k0 + r) * NB + n0 + tx];
    __syncthreads();
    for (int u = threadIdx.x; u < 512; u += 256) {
        const int rr = u >> 4, c = (u & 15) * 2;
        unsigned hi, lo; split2(tile[c][rr], tile[c + 1][rr], hi, lo);
        const size_t off = ((size_t)(n0 + rr) * K + k0 + c) >> 1;
        reinterpret_cast<unsigned*>(dh)[off] = hi;
        reinterpret_cast<unsigned*>(dl)[off] = lo;
    }
}

// ---------------- tensor-core GEMM: 128m x 64n, K=1024, cp.async 2-stage ----
// stage layout (words): AH 0, AL 4608, BH 9216, BL 11520; stage stride 13824
#define SAH 0
#define SAL 4608
#define SBH 9216
#define SBL 11520
#define GSTG 13824

__global__ __launch_bounds__(256, 2) void mma_gemm(
    const __nv_bfloat16* __restrict__ Ah, const __nv_bfloat16* __restrict__ Al,
    const __nv_bfloat16* __restrict__ Bh, const __nv_bfloat16* __restrict__ Bl,
    float* __restrict__ Cout, int mode) {
    extern __shared__ unsigned su[];
    const unsigned sbase = (unsigned)__cvta_generic_to_shared(su);
    const int K = 1024;
    const int m0 = blockIdx.y * 128, n0 = blockIdx.x * 64;
    const int tid = threadIdx.x, lane = tid & 31, wp = tid >> 5;
    const int g = lane >> 2, t = lane & 3;
    const int r0 = wp * 16 + g, r1 = r0 + 8;

    const uint4* pAh = reinterpret_cast<const uint4*>(Ah + (size_t)m0 * K);
    const uint4* pAl = reinterpret_cast<const uint4*>(Al + (size_t)m0 * K);
    const uint4* pBh = reinterpret_cast<const uint4*>(Bh + (size_t)n0 * K);
    const uint4* pBl = reinterpret_cast<const uint4*>(Bl + (size_t)n0 * K);

    float c8[8][4] = {};

#define GLOAD(ST, K0)                                                          \
    {                                                                          \
        const int kc = (K0) >> 3;                                              \
        const unsigned base = sbase + (ST) * (GSTG * 4);                       \
        for (int idx = tid; idx < 2048; idx += 256) {                          \
            const int half = idx >> 10, r = (idx & 1023) >> 3, c = idx & 7;    \
            cpa16(base + (half ? SAL : SAH) * 4 + (r * 9 + c) * 16,            \
                  (half ? pAl : pAh) + (size_t)r * 128 + kc + c);              \
        }                                                                      \
        for (int idx = tid; idx < 1024; idx += 256) {                          \
            const int half = idx >> 9, r = (idx & 511) >> 3, c = idx & 7;      \
            cpa16(base + (half ? SBL : SBH) * 4 + (r * 9 + c) * 16,            \
                  (half ? pBl : pBh) + (size_t)r * 128 + kc + c);              \
        }                                                                      \
        cp_commit();                                                           \
    }

    GLOAD(0, 0)
    for (int it = 0; it < 16; it++) {
        if (it + 1 < 16) { GLOAD((it + 1) & 1, (it + 1) * 64) cp_wait1(); }
        else cp_wait0();
        __syncthreads();
        mma_tile(sbase + (it & 1) * (GSTG * 4), SAH, SAL, SBH, SBL,
                 wp * 16, lane, c8);
        __syncthreads();
    }
#undef GLOAD

    if (mode == 0) {
        const int part = n0 >> 10;
        const int b = m0 >> 11;
        const int mloc = m0 & (N_ - 1);
        const int hh = (n0 & 1023) >> 6;
        const int bh = b * H_ + hh;
        if (part < 2) {
            const float SCp = (part == 0) ? 0.03125f : 1.0f;
            unsigned* uh = reinterpret_cast<unsigned*>(part == 0 ? g_qh : g_kh);
            unsigned* ul = reinterpret_cast<unsigned*>(part == 0 ? g_ql : g_kl);
#pragma unroll
            for (int nt = 0; nt < 8; nt++) {
                const int d = nt * 8 + 2 * t;
                unsigned hi, lo;
                split2(c8[nt][0] * SCp, c8[nt][1] * SCp, hi, lo);
                const size_t o0 = (((size_t)bh * N_ + mloc + r0) * D_ + d) >> 1;
                uh[o0] = hi; ul[o0] = lo;
                split2(c8[nt][2] * SCp, c8[nt][3] * SCp, hi, lo);
                const size_t o1 = (((size_t)bh * N_ + mloc + r1) * D_ + d) >> 1;
                uh[o1] = hi; ul[o1] = lo;
            }
        } else {
            float* vt = reinterpret_cast<float*>(su);
#pragma unroll
            for (int nt = 0; nt < 8; nt++) {
                const int d = nt * 8 + 2 * t;
                vt[(d + 0) * 132 + r0] = c8[nt][0];
                vt[(d + 1) * 132 + r0] = c8[nt][1];
                vt[(d + 0) * 132 + r1] = c8[nt][2];
                vt[(d + 1) * 132 + r1] = c8[nt][3];
            }
            __syncthreads();
            for (int u = tid; u < 1024; u += 256) {
                const int d = u >> 4, cc = (u & 15) * 8;
                unsigned h4[4], l4[4];
#pragma unroll
                for (int p = 0; p < 4; p++)
                    split2(vt[d * 132 + cc + 2 * p], vt[d * 132 + cc + 2 * p + 1],
                           h4[p], l4[p]);
                const size_t off = (((size_t)bh * D_ + d) * N_ + mloc + cc) >> 3;
                reinterpret_cast<uint4*>(g_vh)[off] = make_uint4(h4[0], h4[1], h4[2], h4[3]);
                reinterpret_cast<uint4*>(g_vl)[off] = make_uint4(l4[0], l4[1], l4[2], l4[3]);
            }
        }
    } else {
#pragma unroll
        for (int nt = 0; nt < 8; nt++) {
            const int n = n0 + nt * 8 + 2 * t;
            *reinterpret_cast<float2*>(&Cout[(size_t)(m0 + r0) * DIM_ + n]) =
                make_float2(c8[nt][0], c8[nt][1]);
            *reinterpret_cast<float2*>(&Cout[(size_t)(m0 + r1) * DIM_ + n]) =
                make_float2(c8[nt][2], c8[nt][3]);
        }
    }
}

// ---------------- tensor-core segment attention ----------------
// smem words: QH 0, QL 4608; stages: ST(s)=9216+s*4608 (XH +0, XL +2304);
// WH 18432, WL 23040; dsh 27648; inv 28160; total 28672 w = 114688 B
#define SQH 0
#define SQL 4608
#define SWH 18432
#define SWL 23040

#define ACCSEG(DS, SG, E)                                                      \
    { if ((SG) == 0) DS[0] += (E); else if ((SG) == 1) DS[1] += (E);           \
      else if ((SG) == 2) DS[2] += (E); else DS[3] += (E); }

__global__ __launch_bounds__(256, 2) void attn_mma(const int* __restrict__ mask) {
    extern __shared__ unsigned su[];
    const unsigned sbase = (unsigned)__cvta_generic_to_shared(su);
    float* dshf = reinterpret_cast<float*>(su + 27648);
    float* invf = reinterpret_cast<float*>(su + 28160);
    uint4* su4 = reinterpret_cast<uint4*>(su);

    const int b = blockIdx.z, h = blockIdx.x;
    const int i0 = blockIdx.y * 128;
    const int bh = b * H_ + h;
    const int tid = threadIdx.x;
    const int lane = tid & 31, wp = tid >> 5;
    const int g = lane >> 2, t = lane & 3;
    const int r0 = wp * 16 + g, r1 = r0 + 8;
    const int* mrow = mask + (size_t)b * N_ * N_ + (size_t)i0 * N_;
    float* eblk = g_e + (((size_t)bh * (N_ / 128) + blockIdx.y) * (N_ / 64)) * 8192;

    // load Q tile
    {
        const uint4* gqh = reinterpret_cast<const uint4*>(g_qh + ((size_t)bh * N_ + i0) * D_);
        const uint4* gql = reinterpret_cast<const uint4*>(g_ql + ((size_t)bh * N_ + i0) * D_);
        for (int idx = tid; idx < 1024; idx += 256) {
            const int r = idx >> 3, c = idx & 7;
            su4[(SQH >> 2) + r * 9 + c] = gqh[idx];
            su4[(SQL >> 2) + r * 9 + c] = gql[idx];
        }
    }

    const uint4* gkh = reinterpret_cast<const uint4*>(g_kh + (size_t)bh * N_ * D_);
    const uint4* gkl = reinterpret_cast<const uint4*>(g_kl + (size_t)bh * N_ * D_);
    const uint4* gvh = reinterpret_cast<const uint4*>(g_vh + (size_t)bh * D_ * N_);
    const uint4* gvl = reinterpret_cast<const uint4*>(g_vl + (size_t)bh * D_ * N_);

#define LOADK(ST, JT)                                                          \
    {                                                                          \
        const unsigned base = sbase + (9216 + (ST) * 4608) * 4;                \
        const int jr = (JT) * 512;  /* row jt*64, 8 uint4 per row */           \
        for (int idx = tid; idx < 1024; idx += 256) {                          \
            const int half = idx >> 9, r = (idx & 511) >> 3, c = idx & 7;      \
            cpa16(base + half * 9216 + (r * 9 + c) * 16,                       \
                  (half ? gkl : gkh) + jr + (size_t)r * 8 + c);                \
        }                                                                      \
        cp_commit();                                                           \
    }
#define LOADV(ST, JT)                                                          \
    {                                                                          \
        const unsigned base = sbase + (9216 + (ST) * 4608) * 4;                \
        const int jc = (JT) * 8;  /* uint4 col offset within 2048-wide row */  \
        for (int idx = tid; idx < 1024; idx += 256) {                          \
            const int half = idx >> 9, r = (idx & 511) >> 3, c = idx & 7;      \
            cpa16(base + half * 9216 + (r * 9 + c) * 16,                       \
                  (half ? gvl : gvh) + (size_t)r * 256 + jc + c);              \
        }                                                                      \
        cp_commit();                                                           \
    }

    // ---------------- PASS 1: denominators + e store ----------------
    float ds0[4] = {0.f, 0.f, 0.f, 0.f}, ds1[4] = {0.f, 0.f, 0.f, 0.f};
    LOADK(0, 0)
    for (int jt = 0; jt < 32; jt++) {
        if (jt + 1 < 32) { LOADK((jt + 1) & 1, jt + 1) cp_wait1(); }
        else cp_wait0();
        __syncthreads();
        const int koff = 9216 + (jt & 1) * 4608;
        float c8[8][4] = {};
        mma_tile(sbase, SQH, SQL, koff, koff + 2304, wp * 16, lane, c8);
        __syncthreads();
        float* ew = eblk + ((size_t)jt * 8 + wp) * 1024;
        const int j0 = jt * 64;
#pragma unroll
        for (int nt = 0; nt < 8; nt++) {
            const int jc = j0 + nt * 8 + 2 * t;
            const int2 m0 = *reinterpret_cast<const int2*>(&mrow[(size_t)r0 * N_ + jc]);
            const int2 m1 = *reinterpret_cast<const int2*>(&mrow[(size_t)r1 * N_ + jc]);
            const float e0 = __expf(c8[nt][0]), e1 = __expf(c8[nt][1]);
            const float e2 = __expf(c8[nt][2]), e3 = __expf(c8[nt][3]);
            ACCSEG(ds0, m0.x, e0) ACCSEG(ds0, m0.y, e1)
            ACCSEG(ds1, m1.x, e2) ACCSEG(ds1, m1.y, e3)
            *reinterpret_cast<float2*>(&ew[nt * 128 + g * 8 + 2 * t]) =
                make_float2(e0, e1);
            *reinterpret_cast<float2*>(&ew[nt * 128 + 64 + g * 8 + 2 * t]) =
                make_float2(e2, e3);
        }
    }
#pragma unroll
    for (int s = 0; s < 4; s++) {
        float v0 = ds0[s], v1 = ds1[s];
        v0 += __shfl_xor_sync(0xffffffffu, v0, 1);
        v0 += __shfl_xor_sync(0xffffffffu, v0, 2);
        v1 += __shfl_xor_sync(0xffffffffu, v1, 1);
        v1 += __shfl_xor_sync(0xffffffffu, v1, 2);
        if (t == 0) { dshf[r0 * 4 + s] = v0; dshf[r1 * 4 + s] = v1; }
    }
    __syncthreads();
    for (int idx = tid; idx < 512; idx += 256) {
        const float dv = dshf[idx];
        invf[idx] = (dv == 0.0f) ? 1.0f : 1.0f / dv;
    }
    __syncthreads();

    // ---------------- PASS 2: w = e*invd -> O += w @ V ----------------
    float o8[8][4] = {};
    LOADV(0, 0)
    for (int jt = 0; jt < 32; jt++) {
        if (jt + 1 < 32) LOADV((jt + 1) & 1, jt + 1)
        // build w tile from stored e (independent of V arrival)
        const float* ew = eblk + ((size_t)jt * 8 + wp) * 1024;
        const int j0 = jt * 64;
        const float iv0[4] = {invf[r0 * 4 + 0], invf[r0 * 4 + 1],
                              invf[r0 * 4 + 2], invf[r0 * 4 + 3]};
        const float iv1[4] = {invf[r1 * 4 + 0], invf[r1 * 4 + 1],
                              invf[r1 * 4 + 2], invf[r1 * 4 + 3]};
#pragma unroll
        for (int nt = 0; nt < 8; nt++) {
            const int jc = j0 + nt * 8 + 2 * t;
            const int2 m0 = *reinterpret_cast<const int2*>(&mrow[(size_t)r0 * N_ + jc]);
            const int2 m1 = *reinterpret_cast<const int2*>(&mrow[(size_t)r1 * N_ + jc]);
            const float2 eA = *reinterpret_cast<const float2*>(&ew[nt * 128 + g * 8 + 2 * t]);
            const float2 eB = *reinterpret_cast<const float2*>(&ew[nt * 128 + 64 + g * 8 + 2 * t]);
            unsigned hi, lo;
            split2(eA.x * iv0[m0.x], eA.y * iv0[m0.y], hi, lo);
            su[SWH + r0 * 36 + nt * 4 + t] = hi;
            su[SWL + r0 * 36 + nt * 4 + t] = lo;
            split2(eB.x * iv1[m1.x], eB.y * iv1[m1.y], hi, lo);
            su[SWH + r1 * 36 + nt * 4 + t] = hi;
            su[SWL + r1 * 36 + nt * 4 + t] = lo;
        }
        if (jt + 1 < 32) cp_wait1(); else cp_wait0();
        __syncwarp();
        __syncthreads();
        const int voff = 9216 + (jt & 1) * 4608;
        mma_tile(sbase, SWH, SWL, voff, voff + 2304, wp * 16, lane, o8);
        __syncthreads();
    }
#undef LOADK
#undef LOADV

    // store O as split bf16
    {
        unsigned* ah = reinterpret_cast<unsigned*>(g_ah);
        unsigned* al = reinterpret_cast<unsigned*>(g_al);
#pragma unroll
        for (int nt = 0; nt < 8; nt++) {
            const int d = h * 64 + nt * 8 + 2 * t;
            unsigned hi, lo;
            split2(o8[nt][0], o8[nt][1], hi, lo);
            const size_t o0 = ((size_t)(b * N_ + i0 + r0) * DIM_ + d) >> 1;
            ah[o0] = hi; al[o0] = lo;
            split2(o8[nt][2], o8[nt][3], hi, lo);
            const size_t o1 = ((size_t)(b * N_ + i0 + r1) * DIM_ + d) >> 1;
            ah[o1] = hi; al[o1] = lo;
        }
    }
}

// ---------------------------------------------------------------------------
extern "C" void kernel_launch(void* const* d_in, const int* in_sizes, int n_in,
                              void* d_out, int out_size) {
    const float* features = (const float*)d_in[0];
    const int*   mask     = (const int*)d_in[1];
    const float* W_qkv    = (const float*)d_in[2];
    const float* W_out    = (const float*)d_in[3];
    float* out = (float*)d_out;

    cudaFuncSetAttribute(attn_mma, cudaFuncAttributeMaxDynamicSharedMemorySize, 114688);
    cudaFuncSetAttribute(mma_gemm, cudaFuncAttributeMaxDynamicSharedMemorySize, 110592);

    __nv_bfloat16 *fh, *fl, *wqh, *wql, *woh, *wol, *ah, *al;
    cudaGetSymbolAddress((void**)&fh, g_fh);   cudaGetSymbolAddress((void**)&fl, g_fl);
    cudaGetSymbolAddress((void**)&wqh, g_wqh); cudaGetSymbolAddress((void**)&wql, g_wql);
    cudaGetSymbolAddress((void**)&woh, g_woh); cudaGetSymbolAddress((void**)&wol, g_wol);
    cudaGetSymbolAddress((void**)&ah, g_ah);   cudaGetSymbolAddress((void**)&al, g_al);

    split_f32<<<(M_ * DIM_ / 2 + 255) / 256, 256>>>(features, fh, fl, M_ * DIM_ / 2);
    tsplit_w<<<dim3(3 * DIM_ / 32, DIM_ / 32), 256>>>(W_qkv, wqh, wql, DIM_, 3 * DIM_);
    tsplit_w<<<dim3(DIM_ / 32, DIM_ / 32), 256>>>(W_out, woh, wol, DIM_, DIM_);

    mma_gemm<<<dim3(3 * DIM_ / 64, M_ / 128), 256, 110592>>>(fh, fl, wqh, wql, nullptr, 0);
    attn_mma<<<dim3(H_, N_ / 128, B_), 256, 114688>>>(mask);
    mma_gemm<<<dim3(DIM_ / 64, M_ / 128), 256, 110592>>>(ah, al, woh, wol, out, 1);
}